// round 1
// baseline (speedup 1.0000x reference)
#include <cuda_runtime.h>
#include <math.h>
#include <stdint.h>

// Problem constants (fixed shapes)
#define NB 4
#define NT 2048
#define NH 16
#define NC 1024
#define HD 64              // head dim
#define NM (NB*NT)         // 8192 rows
#define N3C (3*NC)         // 3072

// ---------------- scratch (device globals; no allocation allowed) ------------
__device__ float g_qkv[(size_t)NM * N3C];          // raw qkv   [8192, 3072]
__device__ float g_q[(size_t)NB * NH * NT * HD];   // rope(Q)   [B,H,T,D]
__device__ float g_k[(size_t)NB * NH * NT * HD];   // rope(K)   [B,H,T,D]
__device__ float g_v[(size_t)NB * NH * NT * HD];   // V         [B,H,T,D]
__device__ float g_o[(size_t)NM * NC];             // attn out  [B,T,H*D] = [8192,1024]

// ---------------- SGEMM: C[M,N] = A[M,K] @ B[K,N] + bias[N] ------------------
// BM=128, BN=128, BK=16, 256 threads, 8x8 microtile. M%128==0, N%128==0, K%16==0.
#define BM 128
#define BN 128
#define BK 16
#define TM 8
#define TN 8

__global__ __launch_bounds__(256) void sgemm_bias(
    const float* __restrict__ A, const float* __restrict__ B,
    const float* __restrict__ bias, float* __restrict__ C,
    int M, int N, int K)
{
    __shared__ float As[BK][BM];   // A tile, transposed
    __shared__ float Bs[BK][BN];

    const int bx = blockIdx.x;     // N tile
    const int by = blockIdx.y;     // M tile
    const int tid = threadIdx.x;
    const int tx = tid & 15;
    const int ty = tid >> 4;

    const float* Ab = A + (size_t)by * BM * K;
    const float* Bb = B + (size_t)bx * BN;

    // A load mapping: 128x16 tile = 512 float4; thread loads 2 float4
    const int rowA = tid >> 2;          // 0..63
    const int colA = (tid & 3) * 4;     // 0,4,8,12
    // B load mapping: 16x128 tile = 512 float4; thread loads 2 float4
    const int rowB = tid >> 5;          // 0..7
    const int colB = (tid & 31) * 4;    // 0..124

    float acc[TM][TN];
#pragma unroll
    for (int i = 0; i < TM; i++)
#pragma unroll
        for (int j = 0; j < TN; j++) acc[i][j] = 0.f;

    for (int k0 = 0; k0 < K; k0 += BK) {
#pragma unroll
        for (int r = 0; r < 2; r++) {
            float4 a = *(const float4*)(Ab + (size_t)(rowA + r * 64) * K + k0 + colA);
            As[colA + 0][rowA + r * 64] = a.x;
            As[colA + 1][rowA + r * 64] = a.y;
            As[colA + 2][rowA + r * 64] = a.z;
            As[colA + 3][rowA + r * 64] = a.w;
        }
#pragma unroll
        for (int r = 0; r < 2; r++) {
            *(float4*)(&Bs[rowB + r * 8][colB]) =
                *(const float4*)(Bb + (size_t)(k0 + rowB + r * 8) * N + colB);
        }
        __syncthreads();

#pragma unroll
        for (int k = 0; k < BK; k++) {
            float ra[TM], rb[TN];
#pragma unroll
            for (int i = 0; i < TM; i++) ra[i] = As[k][ty * TM + i];
#pragma unroll
            for (int j = 0; j < TN; j++) rb[j] = Bs[k][tx * TN + j];
#pragma unroll
            for (int i = 0; i < TM; i++)
#pragma unroll
                for (int j = 0; j < TN; j++) acc[i][j] = fmaf(ra[i], rb[j], acc[i][j]);
        }
        __syncthreads();
    }

    // epilogue: bias + store (float4)
    const int crow0 = by * BM + ty * TM;
    const int ccol0 = bx * BN + tx * TN;
#pragma unroll
    for (int i = 0; i < TM; i++) {
#pragma unroll
        for (int j4 = 0; j4 < TN; j4 += 4) {
            float4 o;
            o.x = acc[i][j4 + 0] + bias[ccol0 + j4 + 0];
            o.y = acc[i][j4 + 1] + bias[ccol0 + j4 + 1];
            o.z = acc[i][j4 + 2] + bias[ccol0 + j4 + 2];
            o.w = acc[i][j4 + 3] + bias[ccol0 + j4 + 3];
            *(float4*)(C + (size_t)(crow0 + i) * N + ccol0 + j4) = o;
        }
    }
}

// ---------------- RoPE + split into Q/K/V [B,H,T,D] --------------------------
// torchtune interleaved-pair rope: pairs (2i, 2i+1), freq = base^(-2i/D)
__global__ __launch_bounds__(256) void rope_split(void)
{
    const int p = blockIdx.x * blockDim.x + threadIdx.x;   // pair index
    // total pairs = NM * NH * (HD/2) = 8192*16*32
    const int i   = p & 31;           // pair idx within head dim
    const int h   = (p >> 5) & 15;
    const int row = p >> 9;           // b*T + t
    const int t   = row & (NT - 1);
    const int b   = row >> 11;

    const float inv_freq = __expf(-(float)(2 * i) * (9.210340371976184f / (float)HD));
    const float theta = (float)t * inv_freq;
    float sn, cs;
    sincosf(theta, &sn, &cs);

    const size_t base = (size_t)row * N3C + h * HD + 2 * i;
    const float q0 = g_qkv[base],            q1 = g_qkv[base + 1];
    const float k0 = g_qkv[base + NC],       k1 = g_qkv[base + NC + 1];
    const float v0 = g_qkv[base + 2 * NC],   v1 = g_qkv[base + 2 * NC + 1];

    const size_t oidx = (((size_t)(b * NH + h) * NT + t) * HD) + 2 * i;
    g_q[oidx]     = q0 * cs - q1 * sn;
    g_q[oidx + 1] = q1 * cs + q0 * sn;
    g_k[oidx]     = k0 * cs - k1 * sn;
    g_k[oidx + 1] = k1 * cs + k0 * sn;
    g_v[oidx]     = v0;
    g_v[oidx + 1] = v1;
}

// ---------------- Flash attention (fp32, online softmax) ---------------------
// grid: (T/64, H, B), 256 threads. Q/K/V in [B,H,T,D]. Output [B,T,H*D].
#define BQ 64
#define BKV 64
#define PAD 65

__global__ __launch_bounds__(256) void flash_attn(void)
{
    extern __shared__ float smem[];
    float* Qst = smem;                 // [HD][PAD]  (Qst[d][r])
    float* Kst = Qst + HD * PAD;       // [HD][PAD]  (Kst[d][c])
    float* Vs  = Kst + HD * PAD;       // [BKV][PAD] (Vs[k][d])
    float* Pst = Vs + BKV * PAD;       // [BKV][PAD] (Pst[c][r])

    const int qt = blockIdx.x;
    const int h  = blockIdx.y;
    const int b  = blockIdx.z;
    const int t0 = qt * BQ;

    const float* Qb = g_q + (size_t)(b * NH + h) * NT * HD;
    const float* Kb = g_k + (size_t)(b * NH + h) * NT * HD;
    const float* Vb = g_v + (size_t)(b * NH + h) * NT * HD;

    const int tid = threadIdx.x;
    const int tx = tid & 15;
    const int ty = tid >> 4;
    const int r0 = ty * 4;
    const int c0 = tx * 4;

    // load Q tile (transposed into smem)
#pragma unroll
    for (int p = 0; p < 4; p++) {
        const int r  = (tid >> 4) + p * 16;
        const int d0 = (tid & 15) * 4;
        float4 q4 = *(const float4*)(Qb + (size_t)(t0 + r) * HD + d0);
        Qst[(d0 + 0) * PAD + r] = q4.x;
        Qst[(d0 + 1) * PAD + r] = q4.y;
        Qst[(d0 + 2) * PAD + r] = q4.z;
        Qst[(d0 + 3) * PAD + r] = q4.w;
    }

    float m[4], l[4], o[4][4];
#pragma unroll
    for (int i = 0; i < 4; i++) {
        m[i] = -INFINITY; l[i] = 0.f;
#pragma unroll
        for (int j = 0; j < 4; j++) o[i][j] = 0.f;
    }

    const float scale = 0.125f;   // 1/sqrt(64)

    for (int kt = 0; kt < NT / BKV; kt++) {
        __syncthreads();   // protect Kst/Vs/Pst from previous iteration readers
        // load K (transposed) and V tiles
#pragma unroll
        for (int p = 0; p < 4; p++) {
            const int r  = (tid >> 4) + p * 16;
            const int d0 = (tid & 15) * 4;
            float4 k4 = *(const float4*)(Kb + (size_t)(kt * BKV + r) * HD + d0);
            Kst[(d0 + 0) * PAD + r] = k4.x;
            Kst[(d0 + 1) * PAD + r] = k4.y;
            Kst[(d0 + 2) * PAD + r] = k4.z;
            Kst[(d0 + 3) * PAD + r] = k4.w;
            float4 v4 = *(const float4*)(Vb + (size_t)(kt * BKV + r) * HD + d0);
            Vs[r * PAD + d0 + 0] = v4.x;
            Vs[r * PAD + d0 + 1] = v4.y;
            Vs[r * PAD + d0 + 2] = v4.z;
            Vs[r * PAD + d0 + 3] = v4.w;
        }
        __syncthreads();

        // S = Q @ K^T  (4x4 microtile)
        float s[4][4];
#pragma unroll
        for (int i = 0; i < 4; i++)
#pragma unroll
            for (int j = 0; j < 4; j++) s[i][j] = 0.f;

#pragma unroll 8
        for (int d = 0; d < HD; d++) {
            float ra[4], rb[4];
#pragma unroll
            for (int i = 0; i < 4; i++) ra[i] = Qst[d * PAD + r0 + i];
#pragma unroll
            for (int j = 0; j < 4; j++) rb[j] = Kst[d * PAD + c0 + j];
#pragma unroll
            for (int i = 0; i < 4; i++)
#pragma unroll
                for (int j = 0; j < 4; j++) s[i][j] = fmaf(ra[i], rb[j], s[i][j]);
        }

        // online softmax update
#pragma unroll
        for (int i = 0; i < 4; i++) {
            float mt = -INFINITY;
#pragma unroll
            for (int j = 0; j < 4; j++) {
                s[i][j] *= scale;
                mt = fmaxf(mt, s[i][j]);
            }
#pragma unroll
            for (int off = 8; off; off >>= 1)
                mt = fmaxf(mt, __shfl_xor_sync(0xffffffffu, mt, off, 16));

            const float mn = fmaxf(m[i], mt);
            const float alpha = __expf(m[i] - mn);
            m[i] = mn;

            float rs = 0.f;
#pragma unroll
            for (int j = 0; j < 4; j++) {
                s[i][j] = __expf(s[i][j] - mn);   // now P
                rs += s[i][j];
            }
#pragma unroll
            for (int off = 8; off; off >>= 1)
                rs += __shfl_xor_sync(0xffffffffu, rs, off, 16);

            l[i] = l[i] * alpha + rs;
#pragma unroll
            for (int j = 0; j < 4; j++) o[i][j] *= alpha;
        }

        // write P to smem (transposed: Pst[c][r])
#pragma unroll
        for (int i = 0; i < 4; i++)
#pragma unroll
            for (int j = 0; j < 4; j++)
                Pst[(c0 + j) * PAD + (r0 + i)] = s[i][j];
        __syncthreads();

        // O += P @ V  (cols of o are head-dim, indexed by c0)
#pragma unroll 8
        for (int k = 0; k < BKV; k++) {
            float rp[4], rv[4];
#pragma unroll
            for (int i = 0; i < 4; i++) rp[i] = Pst[k * PAD + r0 + i];
#pragma unroll
            for (int j = 0; j < 4; j++) rv[j] = Vs[k * PAD + c0 + j];
#pragma unroll
            for (int i = 0; i < 4; i++)
#pragma unroll
                for (int j = 0; j < 4; j++) o[i][j] = fmaf(rp[i], rv[j], o[i][j]);
        }
    }

    // epilogue: normalize and store to [B, T, H*D]
#pragma unroll
    for (int i = 0; i < 4; i++) {
        const float inv_l = 1.0f / l[i];
        const size_t orow = ((size_t)b * NT + t0 + r0 + i) * NC + h * HD;
#pragma unroll
        for (int j = 0; j < 4; j++)
            g_o[orow + c0 + j] = o[i][j] * inv_l;
    }
}

// ---------------- launch ------------------------------------------------------
extern "C" void kernel_launch(void* const* d_in, const int* in_sizes, int n_in,
                              void* d_out, int out_size)
{
    const float* x      = (const float*)d_in[0];
    const float* w_qkv  = (const float*)d_in[1];
    const float* b_qkv  = (const float*)d_in[2];
    const float* w_proj = (const float*)d_in[3];
    const float* b_proj = (const float*)d_in[4];
    float* out = (float*)d_out;

    float *p_qkv, *p_o;
    cudaGetSymbolAddress((void**)&p_qkv, g_qkv);
    cudaGetSymbolAddress((void**)&p_o,   g_o);

    const int flash_smem = 2 * HD * PAD * 4 + 2 * BKV * PAD * 4;  // 66560 B
    cudaFuncSetAttribute(flash_attn, cudaFuncAttributeMaxDynamicSharedMemorySize,
                         flash_smem);

    // 1) qkv = x @ w_qkv + b_qkv        [8192,1024]@[1024,3072]
    {
        dim3 grid(N3C / BN, NM / BM);
        sgemm_bias<<<grid, 256>>>(x, w_qkv, b_qkv, p_qkv, NM, N3C, NC);
    }

    // 2) rope + split to [B,H,T,D]
    {
        const int total_pairs = NM * NH * (HD / 2);   // 4,194,304
        rope_split<<<total_pairs / 256, 256>>>();
    }

    // 3) flash attention -> g_o [B,T,C]
    {
        dim3 grid(NT / BQ, NH, NB);
        flash_attn<<<grid, 256, flash_smem>>>();
    }

    // 4) out = g_o @ w_proj + b_proj    [8192,1024]@[1024,1024]
    {
        dim3 grid(NC / BN, NM / BM);
        sgemm_bias<<<grid, 256>>>(p_o, w_proj, b_proj, out, NM, NC, NC);
    }
}

// round 2
// speedup vs baseline: 3.2951x; 3.2951x over previous
#include <cuda_runtime.h>
#include <math.h>
#include <stdint.h>

// Problem constants (fixed shapes)
#define NB 4
#define NT 2048
#define NH 16
#define NC 1024
#define HD 64              // head dim
#define NM (NB*NT)         // 8192 rows
#define N3C (3*NC)         // 3072

// ---------------- scratch (device globals; no allocation allowed) ------------
__device__ float g_qkv[(size_t)NM * N3C];          // raw qkv   [8192, 3072]
__device__ float g_q[(size_t)NB * NH * NT * HD];   // rope(Q) tf32 [B,H,T,D]
__device__ float g_k[(size_t)NB * NH * NT * HD];   // rope(K) tf32 [B,H,T,D]
__device__ float g_v[(size_t)NB * NH * NT * HD];   // V tf32, TRANSPOSED [B,H,D,T]
__device__ float g_o[(size_t)NM * NC];             // attn out  [B,T,H*D]

// ---------------- tf32 helpers ----------------------------------------------
__device__ __forceinline__ uint32_t f32_tf32(float x) {
    uint32_t r;
    asm("cvt.rna.tf32.f32 %0, %1;" : "=r"(r) : "f"(x));
    return r;
}

__device__ __forceinline__ void mma_tf32(float c[4],
                                         uint32_t a0, uint32_t a1, uint32_t a2, uint32_t a3,
                                         uint32_t b0, uint32_t b1) {
    asm volatile(
        "mma.sync.aligned.m16n8k8.row.col.f32.tf32.tf32.f32 "
        "{%0,%1,%2,%3}, {%4,%5,%6,%7}, {%8,%9}, {%0,%1,%2,%3};\n"
        : "+f"(c[0]), "+f"(c[1]), "+f"(c[2]), "+f"(c[3])
        : "r"(a0), "r"(a1), "r"(a2), "r"(a3), "r"(b0), "r"(b1));
}

// ---------------- tf32 GEMM: C[M,N] = A[M,K] @ B[K,N] + bias -----------------
// Block 128x128, K-step 32, 256 threads (8 warps). Warp tile 32x64 (2x8 mma).
#define GAS 36    // As row stride (conflict-free frag reads: (36g+c)%32 = 4g+c)
#define GBS 136   // Bs row stride (conflict-free frag reads: (136k+n)%32 = 8k+n)

__global__ __launch_bounds__(256) void gemm_tf32(
    const float* __restrict__ A, const float* __restrict__ B,
    const float* __restrict__ bias, float* __restrict__ C,
    int M, int N, int K)
{
    __shared__ uint32_t As[128 * GAS];
    __shared__ uint32_t Bs[32 * GBS];

    const int bx = blockIdx.x, by = blockIdx.y;
    const int tid = threadIdx.x;
    const int lane = tid & 31, wid = tid >> 5;
    const int wm = (wid & 3) * 32;        // warp row offset (4 warps along M)
    const int wn = (wid >> 2) * 64;       // warp col offset (2 warps along N)
    const int g = lane >> 2, tg = lane & 3;

    float c[2][8][4];
#pragma unroll
    for (int mi = 0; mi < 2; mi++)
#pragma unroll
        for (int ni = 0; ni < 8; ni++)
#pragma unroll
            for (int j = 0; j < 4; j++) c[mi][ni][j] = 0.f;

    const int arow = tid >> 3;            // 0..31 (plus r*32)
    const int acol = (tid & 7) * 4;
    const int brow = tid >> 5;            // 0..7 (plus r*8)
    const int bcol = (tid & 31) * 4;

    for (int k0 = 0; k0 < K; k0 += 32) {
#pragma unroll
        for (int r = 0; r < 4; r++) {
            const int row = arow + r * 32;
            float4 a4 = *(const float4*)(A + (size_t)(by * 128 + row) * K + k0 + acol);
            As[row * GAS + acol + 0] = f32_tf32(a4.x);
            As[row * GAS + acol + 1] = f32_tf32(a4.y);
            As[row * GAS + acol + 2] = f32_tf32(a4.z);
            As[row * GAS + acol + 3] = f32_tf32(a4.w);
        }
#pragma unroll
        for (int r = 0; r < 4; r++) {
            const int row = brow + r * 8;
            float4 b4 = *(const float4*)(B + (size_t)(k0 + row) * N + bx * 128 + bcol);
            Bs[row * GBS + bcol + 0] = f32_tf32(b4.x);
            Bs[row * GBS + bcol + 1] = f32_tf32(b4.y);
            Bs[row * GBS + bcol + 2] = f32_tf32(b4.z);
            Bs[row * GBS + bcol + 3] = f32_tf32(b4.w);
        }
        __syncthreads();

#pragma unroll
        for (int kk = 0; kk < 4; kk++) {
            const int kb = kk * 8;
            uint32_t a[2][4];
#pragma unroll
            for (int mi = 0; mi < 2; mi++) {
                const int m = wm + mi * 16;
                a[mi][0] = As[(m + g)     * GAS + kb + tg];
                a[mi][1] = As[(m + 8 + g) * GAS + kb + tg];
                a[mi][2] = As[(m + g)     * GAS + kb + 4 + tg];
                a[mi][3] = As[(m + 8 + g) * GAS + kb + 4 + tg];
            }
            uint32_t b[8][2];
#pragma unroll
            for (int ni = 0; ni < 8; ni++) {
                b[ni][0] = Bs[(kb + tg)     * GBS + wn + ni * 8 + g];
                b[ni][1] = Bs[(kb + 4 + tg) * GBS + wn + ni * 8 + g];
            }
#pragma unroll
            for (int mi = 0; mi < 2; mi++)
#pragma unroll
                for (int ni = 0; ni < 8; ni++)
                    mma_tf32(c[mi][ni], a[mi][0], a[mi][1], a[mi][2], a[mi][3],
                             b[ni][0], b[ni][1]);
        }
        __syncthreads();
    }

    // epilogue: bias + store (float2 per c-pair)
#pragma unroll
    for (int mi = 0; mi < 2; mi++) {
        const int r0 = by * 128 + wm + mi * 16 + g;
#pragma unroll
        for (int ni = 0; ni < 8; ni++) {
            const int col = bx * 128 + wn + ni * 8 + 2 * tg;
            const float bz0 = bias[col], bz1 = bias[col + 1];
            float2 v0 = make_float2(c[mi][ni][0] + bz0, c[mi][ni][1] + bz1);
            float2 v1 = make_float2(c[mi][ni][2] + bz0, c[mi][ni][3] + bz1);
            *(float2*)(C + (size_t)r0 * N + col) = v0;
            *(float2*)(C + (size_t)(r0 + 8) * N + col) = v1;
        }
    }
}

// ---------------- RoPE + split Q/K into [B,H,T,D] (tf32-rounded) -------------
__global__ __launch_bounds__(256) void rope_split(void)
{
    const int p = blockIdx.x * blockDim.x + threadIdx.x;   // pair index
    const int i   = p & 31;           // pair idx within head dim
    const int h   = (p >> 5) & 15;
    const int row = p >> 9;           // b*T + t
    const int t   = row & (NT - 1);
    const int b   = row >> 11;

    const float inv_freq = __expf(-(float)(2 * i) * (9.210340371976184f / (float)HD));
    const float theta = (float)t * inv_freq;
    float sn, cs;
    sincosf(theta, &sn, &cs);

    const size_t base = (size_t)row * N3C + h * HD + 2 * i;
    const float q0 = g_qkv[base],      q1 = g_qkv[base + 1];
    const float k0 = g_qkv[base + NC], k1 = g_qkv[base + NC + 1];

    const size_t oidx = (((size_t)(b * NH + h) * NT + t) * HD) + 2 * i;
    g_q[oidx]     = __uint_as_float(f32_tf32(q0 * cs - q1 * sn));
    g_q[oidx + 1] = __uint_as_float(f32_tf32(q1 * cs + q0 * sn));
    g_k[oidx]     = __uint_as_float(f32_tf32(k0 * cs - k1 * sn));
    g_k[oidx + 1] = __uint_as_float(f32_tf32(k1 * cs + k0 * sn));
}

// ---------------- V transpose: qkv[:, 2C + h*64 + d] -> g_v [B,H,D,T] --------
#define TS 67
__global__ __launch_bounds__(256) void transpose_v(void)
{
    __shared__ float Ts[64 * TS];
    const int t0 = blockIdx.x * 64;
    const int h  = blockIdx.y;
    const int b  = blockIdx.z;
    const int tid = threadIdx.x;

#pragma unroll
    for (int p = 0; p < 4; p++) {
        const int lin = tid + p * 256;
        const int trow = lin >> 4;
        const int c4 = (lin & 15) * 4;
        float4 v = *(const float4*)(g_qkv + (size_t)(b * NT + t0 + trow) * N3C
                                    + 2 * NC + h * HD + c4);
        Ts[trow * TS + c4 + 0] = __uint_as_float(f32_tf32(v.x));
        Ts[trow * TS + c4 + 1] = __uint_as_float(f32_tf32(v.y));
        Ts[trow * TS + c4 + 2] = __uint_as_float(f32_tf32(v.z));
        Ts[trow * TS + c4 + 3] = __uint_as_float(f32_tf32(v.w));
    }
    __syncthreads();

#pragma unroll
    for (int p = 0; p < 4; p++) {
        const int lin = tid + p * 256;
        const int d  = lin >> 4;
        const int t4 = (lin & 15) * 4;
        float4 o;
        o.x = Ts[(t4 + 0) * TS + d];
        o.y = Ts[(t4 + 1) * TS + d];
        o.z = Ts[(t4 + 2) * TS + d];
        o.w = Ts[(t4 + 3) * TS + d];
        *(float4*)(g_v + ((size_t)(b * NH + h) * HD + d) * NT + t0 + t4) = o;
    }
}

// ---------------- Flash attention, tf32 mma (BQ=128, BKV=64, 8 warps) --------
#define FST 68   // smem row stride: (68g+c)%32 = 4g+c -> conflict-free frags

__global__ __launch_bounds__(256) void flash_tf32(void)
{
    extern __shared__ uint32_t fsm[];
    uint32_t* Ks = fsm;                 // [64 kv][FST] (kv x d)
    uint32_t* Vt = Ks + 64 * FST;       // [64 d][FST]  (d x kv)
    uint32_t* Ps = Vt + 64 * FST;       // [128 q][FST] (q x d staging, then q x kv P)

    const int qt = blockIdx.x, h = blockIdx.y, b = blockIdx.z;
    const int t0 = qt * 128;
    const int tid = threadIdx.x;
    const int lane = tid & 31, wid = tid >> 5;
    const int g = lane >> 2, tg = lane & 3;
    const int qbase = wid * 16;

    const float* Qb  = g_q + (size_t)(b * NH + h) * NT * HD;
    const float* Kb  = g_k + (size_t)(b * NH + h) * NT * HD;
    const float* Vtb = g_v + (size_t)(b * NH + h) * HD * NT;   // [d][T]

    // stage Q tile [128][64] into Ps (already tf32 bits in gmem)
#pragma unroll
    for (int p = 0; p < 8; p++) {
        const int lin = tid + p * 256;
        const int row = lin >> 4;
        const int c4 = (lin & 15) * 4;
        float4 q4 = *(const float4*)(Qb + (size_t)(t0 + row) * HD + c4);
        Ps[row * FST + c4 + 0] = __float_as_uint(q4.x);
        Ps[row * FST + c4 + 1] = __float_as_uint(q4.y);
        Ps[row * FST + c4 + 2] = __float_as_uint(q4.z);
        Ps[row * FST + c4 + 3] = __float_as_uint(q4.w);
    }
    __syncthreads();

    // load register-resident Q A-fragments (own 16 rows only)
    uint32_t qa[8][4];
#pragma unroll
    for (int kk = 0; kk < 8; kk++) {
        const int kb = kk * 8;
        qa[kk][0] = Ps[(qbase + g)     * FST + kb + tg];
        qa[kk][1] = Ps[(qbase + 8 + g) * FST + kb + tg];
        qa[kk][2] = Ps[(qbase + g)     * FST + kb + 4 + tg];
        qa[kk][3] = Ps[(qbase + 8 + g) * FST + kb + 4 + tg];
    }

    float o[8][4];
#pragma unroll
    for (int ni = 0; ni < 8; ni++)
#pragma unroll
        for (int j = 0; j < 4; j++) o[ni][j] = 0.f;
    float m0 = -INFINITY, m1 = -INFINITY, l0 = 0.f, l1 = 0.f;
    const float scale = 0.125f;

    for (int kt = 0; kt < NT / 64; kt++) {
        __syncthreads();   // all warps done reading Ks/Vt from prev iter
        // load K tile [64 kv][64 d] and Vt tile [64 d][64 kv]
#pragma unroll
        for (int p = 0; p < 4; p++) {
            const int lin = tid + p * 256;
            const int row = lin >> 4;
            const int c4 = (lin & 15) * 4;
            float4 k4 = *(const float4*)(Kb + (size_t)(kt * 64 + row) * HD + c4);
            Ks[row * FST + c4 + 0] = __float_as_uint(k4.x);
            Ks[row * FST + c4 + 1] = __float_as_uint(k4.y);
            Ks[row * FST + c4 + 2] = __float_as_uint(k4.z);
            Ks[row * FST + c4 + 3] = __float_as_uint(k4.w);
            float4 v4 = *(const float4*)(Vtb + (size_t)row * NT + kt * 64 + c4);
            Vt[row * FST + c4 + 0] = __float_as_uint(v4.x);
            Vt[row * FST + c4 + 1] = __float_as_uint(v4.y);
            Vt[row * FST + c4 + 2] = __float_as_uint(v4.z);
            Vt[row * FST + c4 + 3] = __float_as_uint(v4.w);
        }
        __syncthreads();

        // S = Q @ K^T  (per warp: 16 x 64)
        float s[8][4];
#pragma unroll
        for (int ni = 0; ni < 8; ni++)
#pragma unroll
            for (int j = 0; j < 4; j++) s[ni][j] = 0.f;

#pragma unroll
        for (int kk = 0; kk < 8; kk++) {
            const int kb = kk * 8;
#pragma unroll
            for (int ni = 0; ni < 8; ni++) {
                uint32_t b0 = Ks[(ni * 8 + g)     * FST + kb + tg];
                uint32_t b1 = Ks[(ni * 8 + g)     * FST + kb + 4 + tg];
                mma_tf32(s[ni], qa[kk][0], qa[kk][1], qa[kk][2], qa[kk][3], b0, b1);
            }
        }

        // online softmax (rows g and g+8; cols reduce: within thread + quad shfl)
        float mx0 = -INFINITY, mx1 = -INFINITY;
#pragma unroll
        for (int ni = 0; ni < 8; ni++) {
            s[ni][0] *= scale; s[ni][1] *= scale; s[ni][2] *= scale; s[ni][3] *= scale;
            mx0 = fmaxf(mx0, fmaxf(s[ni][0], s[ni][1]));
            mx1 = fmaxf(mx1, fmaxf(s[ni][2], s[ni][3]));
        }
        mx0 = fmaxf(mx0, __shfl_xor_sync(0xffffffffu, mx0, 1));
        mx0 = fmaxf(mx0, __shfl_xor_sync(0xffffffffu, mx0, 2));
        mx1 = fmaxf(mx1, __shfl_xor_sync(0xffffffffu, mx1, 1));
        mx1 = fmaxf(mx1, __shfl_xor_sync(0xffffffffu, mx1, 2));

        const float mn0 = fmaxf(m0, mx0);
        const float mn1 = fmaxf(m1, mx1);
        const float al0 = __expf(m0 - mn0);
        const float al1 = __expf(m1 - mn1);
        m0 = mn0; m1 = mn1;

        float sum0 = 0.f, sum1 = 0.f;
#pragma unroll
        for (int ni = 0; ni < 8; ni++) {
            s[ni][0] = __expf(s[ni][0] - mn0);
            s[ni][1] = __expf(s[ni][1] - mn0);
            s[ni][2] = __expf(s[ni][2] - mn1);
            s[ni][3] = __expf(s[ni][3] - mn1);
            sum0 += s[ni][0] + s[ni][1];
            sum1 += s[ni][2] + s[ni][3];
            o[ni][0] *= al0; o[ni][1] *= al0; o[ni][2] *= al1; o[ni][3] *= al1;
        }
        sum0 += __shfl_xor_sync(0xffffffffu, sum0, 1);
        sum0 += __shfl_xor_sync(0xffffffffu, sum0, 2);
        sum1 += __shfl_xor_sync(0xffffffffu, sum1, 1);
        sum1 += __shfl_xor_sync(0xffffffffu, sum1, 2);
        l0 = l0 * al0 + sum0;
        l1 = l1 * al1 + sum1;

        // store P (tf32) to own rows of Ps
        const int pr0 = qbase + g;
#pragma unroll
        for (int ni = 0; ni < 8; ni++) {
            const int col = ni * 8 + 2 * tg;
            Ps[pr0 * FST + col]           = f32_tf32(s[ni][0]);
            Ps[pr0 * FST + col + 1]       = f32_tf32(s[ni][1]);
            Ps[(pr0 + 8) * FST + col]     = f32_tf32(s[ni][2]);
            Ps[(pr0 + 8) * FST + col + 1] = f32_tf32(s[ni][3]);
        }
        __syncwarp();

        // O += P @ V   (B operand from Vt [d][kv])
#pragma unroll
        for (int kk = 0; kk < 8; kk++) {
            const int kb = kk * 8;
            uint32_t pa0 = Ps[(qbase + g)     * FST + kb + tg];
            uint32_t pa1 = Ps[(qbase + 8 + g) * FST + kb + tg];
            uint32_t pa2 = Ps[(qbase + g)     * FST + kb + 4 + tg];
            uint32_t pa3 = Ps[(qbase + 8 + g) * FST + kb + 4 + tg];
#pragma unroll
            for (int ni = 0; ni < 8; ni++) {
                uint32_t b0 = Vt[(ni * 8 + g) * FST + kb + tg];
                uint32_t b1 = Vt[(ni * 8 + g) * FST + kb + 4 + tg];
                mma_tf32(o[ni], pa0, pa1, pa2, pa3, b0, b1);
            }
        }
        __syncwarp();   // P reads done before next iter's stores
    }

    // epilogue
    const float inv0 = 1.0f / l0;
    const float inv1 = 1.0f / l1;
    const size_t r0 = (size_t)(b * NT + t0 + qbase + g) * NC + h * HD;
    const size_t r1 = r0 + (size_t)8 * NC;
#pragma unroll
    for (int ni = 0; ni < 8; ni++) {
        const int col = ni * 8 + 2 * tg;
        *(float2*)(g_o + r0 + col) = make_float2(o[ni][0] * inv0, o[ni][1] * inv0);
        *(float2*)(g_o + r1 + col) = make_float2(o[ni][2] * inv1, o[ni][3] * inv1);
    }
}

// ---------------- launch ------------------------------------------------------
extern "C" void kernel_launch(void* const* d_in, const int* in_sizes, int n_in,
                              void* d_out, int out_size)
{
    const float* x      = (const float*)d_in[0];
    const float* w_qkv  = (const float*)d_in[1];
    const float* b_qkv  = (const float*)d_in[2];
    const float* w_proj = (const float*)d_in[3];
    const float* b_proj = (const float*)d_in[4];
    float* out = (float*)d_out;

    float *p_qkv, *p_o;
    cudaGetSymbolAddress((void**)&p_qkv, g_qkv);
    cudaGetSymbolAddress((void**)&p_o,   g_o);

    const int flash_smem = (64 * FST + 64 * FST + 128 * FST) * 4;   // 69632 B
    cudaFuncSetAttribute(flash_tf32, cudaFuncAttributeMaxDynamicSharedMemorySize,
                         flash_smem);

    // 1) qkv = x @ w_qkv + b_qkv
    {
        dim3 grid(N3C / 128, NM / 128);
        gemm_tf32<<<grid, 256>>>(x, w_qkv, b_qkv, p_qkv, NM, N3C, NC);
    }
    // 2) rope Q,K -> [B,H,T,D] (tf32)
    {
        const int total_pairs = NM * NH * (HD / 2);
        rope_split<<<total_pairs / 256, 256>>>();
    }
    // 3) V -> [B,H,D,T] (tf32)
    {
        dim3 grid(NT / 64, NH, NB);
        transpose_v<<<grid, 256>>>();
    }
    // 4) flash attention -> g_o [B,T,C]
    {
        dim3 grid(NT / 128, NH, NB);
        flash_tf32<<<grid, 256, flash_smem>>>();
    }
    // 5) out = g_o @ w_proj + b_proj
    {
        dim3 grid(NC / 128, NM / 128);
        gemm_tf32<<<grid, 256>>>(p_o, w_proj, b_proj, out, NM, NC, NC);
    }
}

// round 3
// speedup vs baseline: 3.8631x; 1.1724x over previous
#include <cuda_runtime.h>
#include <math.h>
#include <stdint.h>

// Problem constants (fixed shapes)
#define NB 4
#define NT 2048
#define NH 16
#define NC 1024
#define HD 64              // head dim
#define NM (NB*NT)         // 8192 rows
#define N3C (3*NC)         // 3072

// ---------------- scratch (device globals; no allocation allowed) ------------
__device__ float g_qkv[(size_t)NM * N3C];          // raw qkv   [8192, 3072]
__device__ float g_q[(size_t)NB * NH * NT * HD];   // rope(Q) tf32 [B,H,T,D]
__device__ float g_k[(size_t)NB * NH * NT * HD];   // rope(K) tf32 [B,H,T,D]
__device__ float g_v[(size_t)NB * NH * NT * HD];   // V tf32, TRANSPOSED [B,H,D,T]
__device__ float g_o[(size_t)NM * NC];             // attn out (tf32-rounded)
__device__ float g_xr[(size_t)NM * NC];            // x rounded to tf32
__device__ float g_w1r[(size_t)NC * N3C];          // w_qkv rounded
__device__ float g_w2r[(size_t)NC * NC];           // w_proj rounded

// ---------------- helpers ----------------------------------------------------
__device__ __forceinline__ uint32_t f32_tf32(float x) {
    uint32_t r;
    asm("cvt.rna.tf32.f32 %0, %1;" : "=r"(r) : "f"(x));
    return r;
}

__device__ __forceinline__ void mma_tf32(float c[4],
                                         uint32_t a0, uint32_t a1, uint32_t a2, uint32_t a3,
                                         uint32_t b0, uint32_t b1) {
    asm volatile(
        "mma.sync.aligned.m16n8k8.row.col.f32.tf32.tf32.f32 "
        "{%0,%1,%2,%3}, {%4,%5,%6,%7}, {%8,%9}, {%0,%1,%2,%3};\n"
        : "+f"(c[0]), "+f"(c[1]), "+f"(c[2]), "+f"(c[3])
        : "r"(a0), "r"(a1), "r"(a2), "r"(a3), "r"(b0), "r"(b1));
}

__device__ __forceinline__ void cp16(uint32_t smem_addr, const void* gptr) {
    asm volatile("cp.async.ca.shared.global [%0], [%1], 16;\n"
                 :: "r"(smem_addr), "l"(gptr));
}
__device__ __forceinline__ void cp_commit() {
    asm volatile("cp.async.commit_group;\n");
}
template <int N>
__device__ __forceinline__ void cp_wait() {
    asm volatile("cp.async.wait_group %0;\n" :: "n"(N));
}

// ---------------- tf32 pre-round kernel --------------------------------------
__global__ __launch_bounds__(256) void round_tf32(const float* __restrict__ in,
                                                  float* __restrict__ out) {
    const size_t i = ((size_t)blockIdx.x * 256 + threadIdx.x) * 4;
    float4 v = *(const float4*)(in + i);
    float4 o;
    o.x = __uint_as_float(f32_tf32(v.x));
    o.y = __uint_as_float(f32_tf32(v.y));
    o.z = __uint_as_float(f32_tf32(v.z));
    o.w = __uint_as_float(f32_tf32(v.w));
    *(float4*)(out + i) = o;
}

// ---------------- tf32 GEMM, double-buffered cp.async ------------------------
// C[M,N] = A[M,K] @ B[K,N] + bias. Block 128x128, K-step 32, 256 thr (8 warps).
// Inputs must be pre-rounded to tf32.
#define GAS 36    // As row stride
#define GBS 136   // Bs row stride
#define GSSZ (128*GAS + 32*GBS)   // words per stage = 8960

__global__ __launch_bounds__(256) void gemm_tf32(
    const float* __restrict__ A, const float* __restrict__ B,
    const float* __restrict__ bias, float* __restrict__ C,
    int M, int N, int K)
{
    extern __shared__ uint32_t gsm[];

    const int bx = blockIdx.x, by = blockIdx.y;
    const int tid = threadIdx.x;
    const int lane = tid & 31, wid = tid >> 5;
    const int wm = (wid & 3) * 32;
    const int wn = (wid >> 2) * 64;
    const int g = lane >> 2, tg = lane & 3;

    const int arow = tid >> 3;            // 0..31
    const int acol = (tid & 7) * 4;
    const int brow = tid >> 5;            // 0..7
    const int bcol = (tid & 31) * 4;

    const uint32_t smem_base = (uint32_t)__cvta_generic_to_shared(gsm);

    // async loader for one K-step stage
    auto load_stage = [&](int k0, int stage) {
        const uint32_t as = smem_base + (uint32_t)stage * GSSZ * 4;
        const uint32_t bs = as + 128 * GAS * 4;
#pragma unroll
        for (int r = 0; r < 4; r++) {
            const int row = arow + r * 32;
            cp16(as + (row * GAS + acol) * 4,
                 A + (size_t)(by * 128 + row) * K + k0 + acol);
        }
#pragma unroll
        for (int r = 0; r < 4; r++) {
            const int row = brow + r * 8;
            cp16(bs + (row * GBS + bcol) * 4,
                 B + (size_t)(k0 + row) * N + bx * 128 + bcol);
        }
    };

    float c[2][8][4];
#pragma unroll
    for (int mi = 0; mi < 2; mi++)
#pragma unroll
        for (int ni = 0; ni < 8; ni++)
#pragma unroll
            for (int j = 0; j < 4; j++) c[mi][ni][j] = 0.f;

    const int nsteps = K / 32;
    load_stage(0, 0);
    cp_commit();

    for (int s = 0; s < nsteps; s++) {
        if (s + 1 < nsteps) load_stage((s + 1) * 32, (s + 1) & 1);
        cp_commit();
        cp_wait<1>();
        __syncthreads();

        const uint32_t* As = gsm + (s & 1) * GSSZ;
        const uint32_t* Bs = As + 128 * GAS;

#pragma unroll
        for (int kk = 0; kk < 4; kk++) {
            const int kb = kk * 8;
            uint32_t a[2][4];
#pragma unroll
            for (int mi = 0; mi < 2; mi++) {
                const int m = wm + mi * 16;
                a[mi][0] = As[(m + g)     * GAS + kb + tg];
                a[mi][1] = As[(m + 8 + g) * GAS + kb + tg];
                a[mi][2] = As[(m + g)     * GAS + kb + 4 + tg];
                a[mi][3] = As[(m + 8 + g) * GAS + kb + 4 + tg];
            }
            uint32_t b[8][2];
#pragma unroll
            for (int ni = 0; ni < 8; ni++) {
                b[ni][0] = Bs[(kb + tg)     * GBS + wn + ni * 8 + g];
                b[ni][1] = Bs[(kb + 4 + tg) * GBS + wn + ni * 8 + g];
            }
#pragma unroll
            for (int mi = 0; mi < 2; mi++)
#pragma unroll
                for (int ni = 0; ni < 8; ni++)
                    mma_tf32(c[mi][ni], a[mi][0], a[mi][1], a[mi][2], a[mi][3],
                             b[ni][0], b[ni][1]);
        }
        __syncthreads();
    }

    // epilogue: bias + store
#pragma unroll
    for (int mi = 0; mi < 2; mi++) {
        const int r0 = by * 128 + wm + mi * 16 + g;
#pragma unroll
        for (int ni = 0; ni < 8; ni++) {
            const int col = bx * 128 + wn + ni * 8 + 2 * tg;
            const float bz0 = bias[col], bz1 = bias[col + 1];
            *(float2*)(C + (size_t)r0 * N + col) =
                make_float2(c[mi][ni][0] + bz0, c[mi][ni][1] + bz1);
            *(float2*)(C + (size_t)(r0 + 8) * N + col) =
                make_float2(c[mi][ni][2] + bz0, c[mi][ni][3] + bz1);
        }
    }
}

// ---------------- RoPE + split Q/K into [B,H,T,D] (tf32-rounded) -------------
__global__ __launch_bounds__(256) void rope_split(void)
{
    const int p = blockIdx.x * blockDim.x + threadIdx.x;
    const int i   = p & 31;
    const int h   = (p >> 5) & 15;
    const int row = p >> 9;
    const int t   = row & (NT - 1);
    const int b   = row >> 11;

    const float inv_freq = __expf(-(float)(2 * i) * (9.210340371976184f / (float)HD));
    const float theta = (float)t * inv_freq;
    float sn, cs;
    sincosf(theta, &sn, &cs);

    const size_t base = (size_t)row * N3C + h * HD + 2 * i;
    const float q0 = g_qkv[base],      q1 = g_qkv[base + 1];
    const float k0 = g_qkv[base + NC], k1 = g_qkv[base + NC + 1];

    const size_t oidx = (((size_t)(b * NH + h) * NT + t) * HD) + 2 * i;
    g_q[oidx]     = __uint_as_float(f32_tf32(q0 * cs - q1 * sn));
    g_q[oidx + 1] = __uint_as_float(f32_tf32(q1 * cs + q0 * sn));
    g_k[oidx]     = __uint_as_float(f32_tf32(k0 * cs - k1 * sn));
    g_k[oidx + 1] = __uint_as_float(f32_tf32(k1 * cs + k0 * sn));
}

// ---------------- V transpose: qkv[:, 2C + h*64 + d] -> g_v [B,H,D,T] --------
#define TS 67
__global__ __launch_bounds__(256) void transpose_v(void)
{
    __shared__ float Ts[64 * TS];
    const int t0 = blockIdx.x * 64;
    const int h  = blockIdx.y;
    const int b  = blockIdx.z;
    const int tid = threadIdx.x;

#pragma unroll
    for (int p = 0; p < 4; p++) {
        const int lin = tid + p * 256;
        const int trow = lin >> 4;
        const int c4 = (lin & 15) * 4;
        float4 v = *(const float4*)(g_qkv + (size_t)(b * NT + t0 + trow) * N3C
                                    + 2 * NC + h * HD + c4);
        Ts[trow * TS + c4 + 0] = __uint_as_float(f32_tf32(v.x));
        Ts[trow * TS + c4 + 1] = __uint_as_float(f32_tf32(v.y));
        Ts[trow * TS + c4 + 2] = __uint_as_float(f32_tf32(v.z));
        Ts[trow * TS + c4 + 3] = __uint_as_float(f32_tf32(v.w));
    }
    __syncthreads();

#pragma unroll
    for (int p = 0; p < 4; p++) {
        const int lin = tid + p * 256;
        const int d  = lin >> 4;
        const int t4 = (lin & 15) * 4;
        float4 o;
        o.x = Ts[(t4 + 0) * TS + d];
        o.y = Ts[(t4 + 1) * TS + d];
        o.z = Ts[(t4 + 2) * TS + d];
        o.w = Ts[(t4 + 3) * TS + d];
        *(float4*)(g_v + ((size_t)(b * NH + h) * HD + d) * NT + t0 + t4) = o;
    }
}

// ---------------- Flash attention, tf32 mma, cp.async double-buffered --------
// BQ=128, BKV=64, 8 warps (warp = 16 q rows). P stays in registers (shfl xpose).
#define FST 68
#define FBUF (2 * 64 * FST)      // words per stage (K tile + V tile)

__global__ __launch_bounds__(256) void flash_tf32(void)
{
    extern __shared__ uint32_t fsm[];

    const int qt = blockIdx.x, h = blockIdx.y, b = blockIdx.z;
    const int t0 = qt * 128;
    const int tid = threadIdx.x;
    const int lane = tid & 31, wid = tid >> 5;
    const int g = lane >> 2, tg = lane & 3;
    const int qbase = wid * 16;

    const float* Qb  = g_q + (size_t)(b * NH + h) * NT * HD;
    const float* Kb  = g_k + (size_t)(b * NH + h) * NT * HD;
    const float* Vtb = g_v + (size_t)(b * NH + h) * HD * NT;   // [d][T]

    const uint32_t smem_base = (uint32_t)__cvta_generic_to_shared(fsm);

    // stage Q tile [128][64] into stage-0 area (overwritten later)
#pragma unroll
    for (int p = 0; p < 8; p++) {
        const int lin = tid + p * 256;
        const int row = lin >> 4;
        const int c4 = (lin & 15) * 4;
        float4 q4 = *(const float4*)(Qb + (size_t)(t0 + row) * HD + c4);
        fsm[row * FST + c4 + 0] = __float_as_uint(q4.x);
        fsm[row * FST + c4 + 1] = __float_as_uint(q4.y);
        fsm[row * FST + c4 + 2] = __float_as_uint(q4.z);
        fsm[row * FST + c4 + 3] = __float_as_uint(q4.w);
    }
    __syncthreads();

    uint32_t qa[8][4];
#pragma unroll
    for (int kk = 0; kk < 8; kk++) {
        const int kb = kk * 8;
        qa[kk][0] = fsm[(qbase + g)     * FST + kb + tg];
        qa[kk][1] = fsm[(qbase + 8 + g) * FST + kb + tg];
        qa[kk][2] = fsm[(qbase + g)     * FST + kb + 4 + tg];
        qa[kk][3] = fsm[(qbase + 8 + g) * FST + kb + 4 + tg];
    }
    __syncthreads();   // all qa reads done before K0/V0 overwrite

    // async K/V tile loader
    auto load_tile = [&](int kt, int buf) {
        const uint32_t base = smem_base + (uint32_t)buf * FBUF * 4;
#pragma unroll
        for (int p = 0; p < 4; p++) {
            const int lin = tid + p * 256;
            const int row = lin >> 4;
            const int c4 = (lin & 15) * 4;
            cp16(base + (row * FST + c4) * 4,
                 Kb + (size_t)(kt * 64 + row) * HD + c4);
            cp16(base + (64 * FST + row * FST + c4) * 4,
                 Vtb + (size_t)row * NT + kt * 64 + c4);
        }
    };

    float o[8][4];
#pragma unroll
    for (int ni = 0; ni < 8; ni++)
#pragma unroll
        for (int j = 0; j < 4; j++) o[ni][j] = 0.f;
    float m0 = -INFINITY, m1 = -INFINITY, l0 = 0.f, l1 = 0.f;
    const float scale = 0.125f;

    load_tile(0, 0);
    cp_commit();

    const int srcq0 = (lane & ~3) | (tg >> 1);
    const int srcq1 = srcq0 + 2;
    const bool odd = (tg & 1);

    for (int kt = 0; kt < NT / 64; kt++) {
        if (kt + 1 < NT / 64) load_tile(kt + 1, (kt + 1) & 1);
        cp_commit();
        cp_wait<1>();
        __syncthreads();

        const uint32_t* Ks = fsm + (kt & 1) * FBUF;
        const uint32_t* Vt = Ks + 64 * FST;

        // S = Q @ K^T
        float s[8][4];
#pragma unroll
        for (int ni = 0; ni < 8; ni++)
#pragma unroll
            for (int j = 0; j < 4; j++) s[ni][j] = 0.f;

#pragma unroll
        for (int kk = 0; kk < 8; kk++) {
            const int kb = kk * 8;
#pragma unroll
            for (int ni = 0; ni < 8; ni++) {
                uint32_t b0 = Ks[(ni * 8 + g) * FST + kb + tg];
                uint32_t b1 = Ks[(ni * 8 + g) * FST + kb + 4 + tg];
                mma_tf32(s[ni], qa[kk][0], qa[kk][1], qa[kk][2], qa[kk][3], b0, b1);
            }
        }

        // online softmax (rows g and g+8)
        float mx0 = -INFINITY, mx1 = -INFINITY;
#pragma unroll
        for (int ni = 0; ni < 8; ni++) {
            s[ni][0] *= scale; s[ni][1] *= scale; s[ni][2] *= scale; s[ni][3] *= scale;
            mx0 = fmaxf(mx0, fmaxf(s[ni][0], s[ni][1]));
            mx1 = fmaxf(mx1, fmaxf(s[ni][2], s[ni][3]));
        }
        mx0 = fmaxf(mx0, __shfl_xor_sync(0xffffffffu, mx0, 1));
        mx0 = fmaxf(mx0, __shfl_xor_sync(0xffffffffu, mx0, 2));
        mx1 = fmaxf(mx1, __shfl_xor_sync(0xffffffffu, mx1, 1));
        mx1 = fmaxf(mx1, __shfl_xor_sync(0xffffffffu, mx1, 2));

        const float mn0 = fmaxf(m0, mx0);
        const float mn1 = fmaxf(m1, mx1);
        const float al0 = __expf(m0 - mn0);
        const float al1 = __expf(m1 - mn1);
        m0 = mn0; m1 = mn1;

        float sum0 = 0.f, sum1 = 0.f;
#pragma unroll
        for (int ni = 0; ni < 8; ni++) {
            s[ni][0] = __expf(s[ni][0] - mn0);
            s[ni][1] = __expf(s[ni][1] - mn0);
            s[ni][2] = __expf(s[ni][2] - mn1);
            s[ni][3] = __expf(s[ni][3] - mn1);
            sum0 += s[ni][0] + s[ni][1];
            sum1 += s[ni][2] + s[ni][3];
            o[ni][0] *= al0; o[ni][1] *= al0; o[ni][2] *= al1; o[ni][3] *= al1;
        }
        sum0 += __shfl_xor_sync(0xffffffffu, sum0, 1);
        sum0 += __shfl_xor_sync(0xffffffffu, sum0, 2);
        sum1 += __shfl_xor_sync(0xffffffffu, sum1, 1);
        sum1 += __shfl_xor_sync(0xffffffffu, sum1, 2);
        l0 = l0 * al0 + sum0;
        l1 = l1 * al1 + sum1;

        // O += P @ V, P A-frags built in-register via quad shfl transpose
#pragma unroll
        for (int kk = 0; kk < 8; kk++) {
            const int kb = kk * 8;
            // C-frag (cols 2tg,2tg+1) -> A-frag (cols tg, tg+4)
            float e0 = __shfl_sync(0xffffffffu, s[kk][0], srcq0);
            float e1 = __shfl_sync(0xffffffffu, s[kk][1], srcq0);
            float e2 = __shfl_sync(0xffffffffu, s[kk][2], srcq0);
            float e3 = __shfl_sync(0xffffffffu, s[kk][3], srcq0);
            float f0 = __shfl_sync(0xffffffffu, s[kk][0], srcq1);
            float f1 = __shfl_sync(0xffffffffu, s[kk][1], srcq1);
            float f2 = __shfl_sync(0xffffffffu, s[kk][2], srcq1);
            float f3 = __shfl_sync(0xffffffffu, s[kk][3], srcq1);
            uint32_t pa0 = f32_tf32(odd ? e1 : e0);
            uint32_t pa1 = f32_tf32(odd ? e3 : e2);
            uint32_t pa2 = f32_tf32(odd ? f1 : f0);
            uint32_t pa3 = f32_tf32(odd ? f3 : f2);
#pragma unroll
            for (int ni = 0; ni < 8; ni++) {
                uint32_t b0 = Vt[(ni * 8 + g) * FST + kb + tg];
                uint32_t b1 = Vt[(ni * 8 + g) * FST + kb + 4 + tg];
                mma_tf32(o[ni], pa0, pa1, pa2, pa3, b0, b1);
            }
        }
        __syncthreads();   // all reads of this stage done before next overwrite
    }

    // epilogue: normalize, round to tf32 (proj GEMM consumes this), store
    const float inv0 = 1.0f / l0;
    const float inv1 = 1.0f / l1;
    const size_t r0 = (size_t)(b * NT + t0 + qbase + g) * NC + h * HD;
    const size_t r1 = r0 + (size_t)8 * NC;
#pragma unroll
    for (int ni = 0; ni < 8; ni++) {
        const int col = ni * 8 + 2 * tg;
        *(float2*)(g_o + r0 + col) = make_float2(
            __uint_as_float(f32_tf32(o[ni][0] * inv0)),
            __uint_as_float(f32_tf32(o[ni][1] * inv0)));
        *(float2*)(g_o + r1 + col) = make_float2(
            __uint_as_float(f32_tf32(o[ni][2] * inv1)),
            __uint_as_float(f32_tf32(o[ni][3] * inv1)));
    }
}

// ---------------- launch ------------------------------------------------------
extern "C" void kernel_launch(void* const* d_in, const int* in_sizes, int n_in,
                              void* d_out, int out_size)
{
    const float* x      = (const float*)d_in[0];
    const float* w_qkv  = (const float*)d_in[1];
    const float* b_qkv  = (const float*)d_in[2];
    const float* w_proj = (const float*)d_in[3];
    const float* b_proj = (const float*)d_in[4];
    float* out = (float*)d_out;

    float *p_qkv, *p_o, *p_xr, *p_w1r, *p_w2r;
    cudaGetSymbolAddress((void**)&p_qkv, g_qkv);
    cudaGetSymbolAddress((void**)&p_o,   g_o);
    cudaGetSymbolAddress((void**)&p_xr,  g_xr);
    cudaGetSymbolAddress((void**)&p_w1r, g_w1r);
    cudaGetSymbolAddress((void**)&p_w2r, g_w2r);

    const int gemm_smem  = 2 * GSSZ * 4;          // 71680 B
    const int flash_smem = 2 * FBUF * 4;          // 69632 B
    static bool attr_done = false;
    cudaFuncSetAttribute(gemm_tf32, cudaFuncAttributeMaxDynamicSharedMemorySize,
                         gemm_smem);
    cudaFuncSetAttribute(flash_tf32, cudaFuncAttributeMaxDynamicSharedMemorySize,
                         flash_smem);
    (void)attr_done;

    // 0) pre-round inputs to tf32 (rna), so cp.async paths keep rna accuracy
    round_tf32<<<(NM * NC) / 1024, 256>>>(x, p_xr);
    round_tf32<<<(NC * N3C) / 1024, 256>>>(w_qkv, p_w1r);
    round_tf32<<<(NC * NC) / 1024, 256>>>(w_proj, p_w2r);

    // 1) qkv = x @ w_qkv + b_qkv
    {
        dim3 grid(N3C / 128, NM / 128);
        gemm_tf32<<<grid, 256, gemm_smem>>>(p_xr, p_w1r, b_qkv, p_qkv, NM, N3C, NC);
    }
    // 2) rope Q,K -> [B,H,T,D] (tf32)
    {
        const int total_pairs = NM * NH * (HD / 2);
        rope_split<<<total_pairs / 256, 256>>>();
    }
    // 3) V -> [B,H,D,T] (tf32)
    {
        dim3 grid(NT / 64, NH, NB);
        transpose_v<<<grid, 256>>>();
    }
    // 4) flash attention -> g_o [B,T,C] (tf32-rounded)
    {
        dim3 grid(NT / 128, NH, NB);
        flash_tf32<<<grid, 256, flash_smem>>>();
    }
    // 5) out = g_o @ w_proj + b_proj
    {
        dim3 grid(NC / 128, NM / 128);
        gemm_tf32<<<grid, 256, gemm_smem>>>(p_o, p_w2r, b_proj, out, NM, NC, NC);
    }
}

// round 5
// speedup vs baseline: 4.0829x; 1.0569x over previous
#include <cuda_runtime.h>
#include <math.h>
#include <stdint.h>

// Problem constants (fixed shapes)
#define NB 4
#define NT 2048
#define NH 16
#define NC 1024
#define HD 64
#define NM (NB*NT)         // 8192
#define N3C (3*NC)         // 3072

// ---------------- scratch ----------------------------------------------------
__device__ float g_qkv[(size_t)NM * N3C];
__device__ float g_q[(size_t)NB * NH * NT * HD];
__device__ float g_k[(size_t)NB * NH * NT * HD];
__device__ float g_v[(size_t)NB * NH * NT * HD];   // V tf32, [B,H,D,T]
__device__ float g_o[(size_t)NM * NC];             // attn out (tf32-rounded)
__device__ float g_xr[(size_t)NM * NC];            // x rounded to tf32
__device__ float g_w1t[(size_t)N3C * NC];          // w_qkv^T rounded [3072][1024]
__device__ float g_w2t[(size_t)NC * NC];           // w_proj^T rounded [1024][1024]

// ---------------- helpers ----------------------------------------------------
__device__ __forceinline__ uint32_t f32_tf32(float x) {
    uint32_t r;
    asm("cvt.rna.tf32.f32 %0, %1;" : "=r"(r) : "f"(x));
    return r;
}

__device__ __forceinline__ void mma_tf32(float c[4],
                                         uint32_t a0, uint32_t a1, uint32_t a2, uint32_t a3,
                                         uint32_t b0, uint32_t b1) {
    asm volatile(
        "mma.sync.aligned.m16n8k8.row.col.f32.tf32.tf32.f32 "
        "{%0,%1,%2,%3}, {%4,%5,%6,%7}, {%8,%9}, {%0,%1,%2,%3};\n"
        : "+f"(c[0]), "+f"(c[1]), "+f"(c[2]), "+f"(c[3])
        : "r"(a0), "r"(a1), "r"(a2), "r"(a3), "r"(b0), "r"(b1));
}

__device__ __forceinline__ void ldm_x4(uint32_t& r0, uint32_t& r1,
                                       uint32_t& r2, uint32_t& r3, uint32_t addr) {
    asm volatile("ldmatrix.sync.aligned.m8n8.x4.shared.b16 {%0,%1,%2,%3}, [%4];"
                 : "=r"(r0), "=r"(r1), "=r"(r2), "=r"(r3) : "r"(addr));
}

__device__ __forceinline__ void cp16(uint32_t smem_addr, const void* gptr) {
    asm volatile("cp.async.cg.shared.global [%0], [%1], 16;\n"
                 :: "r"(smem_addr), "l"(gptr));
}
__device__ __forceinline__ void cp_commit() {
    asm volatile("cp.async.commit_group;\n");
}
template <int N>
__device__ __forceinline__ void cp_wait() {
    asm volatile("cp.async.wait_group %0;\n" :: "n"(N));
}
__device__ __forceinline__ uint32_t smem_u32(const void* p) {
    return (uint32_t)__cvta_generic_to_shared(p);
}

// ---------------- tf32 pre-round ---------------------------------------------
__global__ __launch_bounds__(256) void round_tf32(const float* __restrict__ in,
                                                  float* __restrict__ out) {
    const size_t i = ((size_t)blockIdx.x * 256 + threadIdx.x) * 4;
    float4 v = *(const float4*)(in + i);
    float4 o;
    o.x = __uint_as_float(f32_tf32(v.x));
    o.y = __uint_as_float(f32_tf32(v.y));
    o.z = __uint_as_float(f32_tf32(v.z));
    o.w = __uint_as_float(f32_tf32(v.w));
    *(float4*)(out + i) = o;
}

// transpose + round: in [R][Cc] -> out [Cc][R], rna-tf32
__global__ __launch_bounds__(256) void transpose_round(const float* __restrict__ in,
                                                       float* __restrict__ out,
                                                       int R, int Cc) {
    __shared__ float t[32][33];
    const int c0 = blockIdx.x * 32, r0 = blockIdx.y * 32;
    const int tx = threadIdx.x & 31, ty = threadIdx.x >> 5;
#pragma unroll
    for (int i = 0; i < 32; i += 8)
        t[ty + i][tx] = in[(size_t)(r0 + ty + i) * Cc + c0 + tx];
    __syncthreads();
#pragma unroll
    for (int i = 0; i < 32; i += 8)
        out[(size_t)(c0 + ty + i) * R + r0 + tx] =
            __uint_as_float(f32_tf32(t[tx][ty + i]));
}

// ---------------- tf32 GEMM, ldmatrix + cp.async double-buffered -------------
// C[M,N] = A[M,K] @ Bt[N,K]^T + bias. Block 128x128, K-step 32, 256 threads.
// Both smem operands stored [row][32k], stride GST=36 words (LDSM conflict-free).
#define GST 36
#define GSTAGE (2 * 128 * GST)     // words per stage = 9216

__global__ __launch_bounds__(256) void gemm_tf32(
    const float* __restrict__ A, const float* __restrict__ Bt,
    const float* __restrict__ bias, float* __restrict__ C,
    int M, int N, int K)
{
    extern __shared__ uint32_t gsm[];

    const int bx = blockIdx.x, by = blockIdx.y;
    const int tid = threadIdx.x;
    const int lane = tid & 31, wid = tid >> 5;
    const int wm = (wid & 3) * 32;
    const int wn = (wid >> 2) * 64;
    const int g = lane >> 2, tg = lane & 3;
    (void)g; (void)tg;

    const uint32_t smem_base = smem_u32(gsm);

    // ldmatrix per-thread offsets (bytes)
    const int ltile = lane >> 3, lr = lane & 7;
    const uint32_t a_off = ((wm + (ltile & 1) * 8 + lr) * GST + (ltile >> 1) * 4) * 4;
    const uint32_t b_off = ((wn + (ltile >> 1) * 8 + lr) * GST + (ltile & 1) * 4) * 4;

    const float* Ab  = A  + (size_t)(by * 128) * K;
    const float* Btb = Bt + (size_t)(bx * 128) * K;

    auto load_stage = [&](int k0, int st) {
        const uint32_t base = smem_base + (uint32_t)st * GSTAGE * 4;
#pragma unroll
        for (int t = 0; t < 4; t++) {
            const int ci = tid + t * 256;          // 0..1023
            const int row = ci >> 3, cw = (ci & 7) * 4;
            cp16(base + (row * GST + cw) * 4,
                 Ab + (size_t)row * K + k0 + cw);
            cp16(base + (128 * GST + row * GST + cw) * 4,
                 Btb + (size_t)row * K + k0 + cw);
        }
    };

    float c[2][8][4];
#pragma unroll
    for (int mi = 0; mi < 2; mi++)
#pragma unroll
        for (int ni = 0; ni < 8; ni++)
#pragma unroll
            for (int j = 0; j < 4; j++) c[mi][ni][j] = 0.f;

    const int nsteps = K / 32;
    load_stage(0, 0);
    cp_commit();

    for (int s = 0; s < nsteps; s++) {
        if (s + 1 < nsteps) load_stage((s + 1) * 32, (s + 1) & 1);
        cp_commit();
        cp_wait<1>();
        __syncthreads();

        const uint32_t sb = smem_base + (uint32_t)(s & 1) * GSTAGE * 4;
        const uint32_t a_addr = sb + a_off;
        const uint32_t b_addr = sb + 128 * GST * 4 + b_off;

#pragma unroll
        for (int kk = 0; kk < 4; kk++) {
            uint32_t a[2][4];
#pragma unroll
            for (int mi = 0; mi < 2; mi++)
                ldm_x4(a[mi][0], a[mi][1], a[mi][2], a[mi][3],
                       a_addr + mi * (16 * GST * 4) + kk * 32);
#pragma unroll
            for (int p = 0; p < 4; p++) {
                uint32_t b0, b1, b2, b3;
                ldm_x4(b0, b1, b2, b3, b_addr + p * (16 * GST * 4) + kk * 32);
                mma_tf32(c[0][2 * p],     a[0][0], a[0][1], a[0][2], a[0][3], b0, b1);
                mma_tf32(c[0][2 * p + 1], a[0][0], a[0][1], a[0][2], a[0][3], b2, b3);
                mma_tf32(c[1][2 * p],     a[1][0], a[1][1], a[1][2], a[1][3], b0, b1);
                mma_tf32(c[1][2 * p + 1], a[1][0], a[1][1], a[1][2], a[1][3], b2, b3);
            }
        }
        __syncthreads();
    }

    // epilogue
    const int gg = lane >> 2, tt = lane & 3;
#pragma unroll
    for (int mi = 0; mi < 2; mi++) {
        const int r0 = by * 128 + wm + mi * 16 + gg;
#pragma unroll
        for (int ni = 0; ni < 8; ni++) {
            const int col = bx * 128 + wn + ni * 8 + 2 * tt;
            const float bz0 = bias[col], bz1 = bias[col + 1];
            *(float2*)(C + (size_t)r0 * N + col) =
                make_float2(c[mi][ni][0] + bz0, c[mi][ni][1] + bz1);
            *(float2*)(C + (size_t)(r0 + 8) * N + col) =
                make_float2(c[mi][ni][2] + bz0, c[mi][ni][3] + bz1);
        }
    }
}

// ---------------- RoPE + split Q/K into [B,H,T,D] (tf32-rounded) -------------
__global__ __launch_bounds__(256) void rope_split(void)
{
    const int p = blockIdx.x * blockDim.x + threadIdx.x;
    const int i   = p & 31;
    const int h   = (p >> 5) & 15;
    const int row = p >> 9;
    const int t   = row & (NT - 1);
    const int b   = row >> 11;

    const float inv_freq = __expf(-(float)(2 * i) * (9.210340371976184f / (float)HD));
    const float theta = (float)t * inv_freq;
    float sn, cs;
    sincosf(theta, &sn, &cs);

    const size_t base = (size_t)row * N3C + h * HD + 2 * i;
    const float q0 = g_qkv[base],      q1 = g_qkv[base + 1];
    const float k0 = g_qkv[base + NC], k1 = g_qkv[base + NC + 1];

    const size_t oidx = (((size_t)(b * NH + h) * NT + t) * HD) + 2 * i;
    g_q[oidx]     = __uint_as_float(f32_tf32(q0 * cs - q1 * sn));
    g_q[oidx + 1] = __uint_as_float(f32_tf32(q1 * cs + q0 * sn));
    g_k[oidx]     = __uint_as_float(f32_tf32(k0 * cs - k1 * sn));
    g_k[oidx + 1] = __uint_as_float(f32_tf32(k1 * cs + k0 * sn));
}

// ---------------- V transpose: qkv[:, 2C + h*64 + d] -> g_v [B,H,D,T] --------
#define TS 67
__global__ __launch_bounds__(256) void transpose_v(void)
{
    __shared__ float Ts[64 * TS];
    const int t0 = blockIdx.x * 64;
    const int h  = blockIdx.y;
    const int b  = blockIdx.z;
    const int tid = threadIdx.x;

#pragma unroll
    for (int p = 0; p < 4; p++) {
        const int lin = tid + p * 256;
        const int trow = lin >> 4;
        const int c4 = (lin & 15) * 4;
        float4 v = *(const float4*)(g_qkv + (size_t)(b * NT + t0 + trow) * N3C
                                    + 2 * NC + h * HD + c4);
        Ts[trow * TS + c4 + 0] = __uint_as_float(f32_tf32(v.x));
        Ts[trow * TS + c4 + 1] = __uint_as_float(f32_tf32(v.y));
        Ts[trow * TS + c4 + 2] = __uint_as_float(f32_tf32(v.z));
        Ts[trow * TS + c4 + 3] = __uint_as_float(f32_tf32(v.w));
    }
    __syncthreads();

#pragma unroll
    for (int p = 0; p < 4; p++) {
        const int lin = tid + p * 256;
        const int d  = lin >> 4;
        const int t4 = (lin & 15) * 4;
        float4 o;
        o.x = Ts[(t4 + 0) * TS + d];
        o.y = Ts[(t4 + 1) * TS + d];
        o.z = Ts[(t4 + 2) * TS + d];
        o.w = Ts[(t4 + 3) * TS + d];
        *(float4*)(g_v + ((size_t)(b * NH + h) * HD + d) * NT + t0 + t4) = o;
    }
}

// ---------------- Flash attention, tf32 mma + ldmatrix, double-buffered ------
#define FST 68
#define FBUF (2 * 64 * FST)

__global__ __launch_bounds__(256) void flash_tf32(void)
{
    extern __shared__ uint32_t fsm[];

    const int qt = blockIdx.x, h = blockIdx.y, b = blockIdx.z;
    const int t0 = qt * 128;
    const int tid = threadIdx.x;
    const int lane = tid & 31, wid = tid >> 5;
    const int g = lane >> 2, tg = lane & 3;
    const int qbase = wid * 16;

    const float* Qb  = g_q + (size_t)(b * NH + h) * NT * HD;
    const float* Kb  = g_k + (size_t)(b * NH + h) * NT * HD;
    const float* Vtb = g_v + (size_t)(b * NH + h) * HD * NT;

    const uint32_t smem_base = smem_u32(fsm);

    // ldmatrix per-thread offset (bytes) into a [row][FST] tile
    const int ltile = lane >> 3, lr = lane & 7;
    const uint32_t fb_off = (((ltile >> 1) * 8 + lr) * FST + (ltile & 1) * 4) * 4;

    // stage Q tile [128][64] into stage-0 area (overwritten later)
#pragma unroll
    for (int p = 0; p < 8; p++) {
        const int lin = tid + p * 256;
        const int row = lin >> 4;
        const int c4 = (lin & 15) * 4;
        float4 q4 = *(const float4*)(Qb + (size_t)(t0 + row) * HD + c4);
        fsm[row * FST + c4 + 0] = __float_as_uint(q4.x);
        fsm[row * FST + c4 + 1] = __float_as_uint(q4.y);
        fsm[row * FST + c4 + 2] = __float_as_uint(q4.z);
        fsm[row * FST + c4 + 3] = __float_as_uint(q4.w);
    }
    __syncthreads();

    uint32_t qa[8][4];
#pragma unroll
    for (int kk = 0; kk < 8; kk++) {
        const int kb = kk * 8;
        qa[kk][0] = fsm[(qbase + g)     * FST + kb + tg];
        qa[kk][1] = fsm[(qbase + 8 + g) * FST + kb + tg];
        qa[kk][2] = fsm[(qbase + g)     * FST + kb + 4 + tg];
        qa[kk][3] = fsm[(qbase + 8 + g) * FST + kb + 4 + tg];
    }
    __syncthreads();

    auto load_tile = [&](int kt, int buf) {
        const uint32_t base = smem_base + (uint32_t)buf * FBUF * 4;
#pragma unroll
        for (int p = 0; p < 4; p++) {
            const int lin = tid + p * 256;
            const int row = lin >> 4;
            const int c4 = (lin & 15) * 4;
            cp16(base + (row * FST + c4) * 4,
                 Kb + (size_t)(kt * 64 + row) * HD + c4);
            cp16(base + (64 * FST + row * FST + c4) * 4,
                 Vtb + (size_t)row * NT + kt * 64 + c4);
        }
    };

    float o[8][4];
#pragma unroll
    for (int ni = 0; ni < 8; ni++)
#pragma unroll
        for (int j = 0; j < 4; j++) o[ni][j] = 0.f;
    float m0 = -INFINITY, m1 = -INFINITY, l0 = 0.f, l1 = 0.f;
    const float scale = 0.125f;

    load_tile(0, 0);
    cp_commit();

    const int srcq0 = (lane & ~3) | (tg >> 1);
    const int srcq1 = srcq0 + 2;
    const bool odd = (tg & 1);

    for (int kt = 0; kt < NT / 64; kt++) {
        if (kt + 1 < NT / 64) load_tile(kt + 1, (kt + 1) & 1);
        cp_commit();
        cp_wait<1>();
        __syncthreads();

        const uint32_t k_addr = smem_base + (uint32_t)(kt & 1) * FBUF * 4 + fb_off;
        const uint32_t v_addr = k_addr + 64 * FST * 4;

        // S = Q @ K^T
        float s[8][4];
#pragma unroll
        for (int ni = 0; ni < 8; ni++)
#pragma unroll
            for (int j = 0; j < 4; j++) s[ni][j] = 0.f;

#pragma unroll
        for (int kk = 0; kk < 8; kk++) {
#pragma unroll
            for (int p = 0; p < 4; p++) {
                uint32_t b0, b1, b2, b3;
                ldm_x4(b0, b1, b2, b3, k_addr + p * (16 * FST * 4) + kk * 32);
                mma_tf32(s[2 * p],     qa[kk][0], qa[kk][1], qa[kk][2], qa[kk][3], b0, b1);
                mma_tf32(s[2 * p + 1], qa[kk][0], qa[kk][1], qa[kk][2], qa[kk][3], b2, b3);
            }
        }

        // online softmax (rows g and g+8)
        float mx0 = -INFINITY, mx1 = -INFINITY;
#pragma unroll
        for (int ni = 0; ni < 8; ni++) {
            s[ni][0] *= scale; s[ni][1] *= scale; s[ni][2] *= scale; s[ni][3] *= scale;
            mx0 = fmaxf(mx0, fmaxf(s[ni][0], s[ni][1]));
            mx1 = fmaxf(mx1, fmaxf(s[ni][2], s[ni][3]));
        }
        mx0 = fmaxf(mx0, __shfl_xor_sync(0xffffffffu, mx0, 1));
        mx0 = fmaxf(mx0, __shfl_xor_sync(0xffffffffu, mx0, 2));
        mx1 = fmaxf(mx1, __shfl_xor_sync(0xffffffffu, mx1, 1));
        mx1 = fmaxf(mx1, __shfl_xor_sync(0xffffffffu, mx1, 2));

        const float mn0 = fmaxf(m0, mx0);
        const float mn1 = fmaxf(m1, mx1);
        const float al0 = __expf(m0 - mn0);
        const float al1 = __expf(m1 - mn1);
        m0 = mn0; m1 = mn1;

        float sum0 = 0.f, sum1 = 0.f;
#pragma unroll
        for (int ni = 0; ni < 8; ni++) {
            s[ni][0] = __expf(s[ni][0] - mn0);
            s[ni][1] = __expf(s[ni][1] - mn0);
            s[ni][2] = __expf(s[ni][2] - mn1);
            s[ni][3] = __expf(s[ni][3] - mn1);
            sum0 += s[ni][0] + s[ni][1];
            sum1 += s[ni][2] + s[ni][3];
            o[ni][0] *= al0; o[ni][1] *= al0; o[ni][2] *= al1; o[ni][3] *= al1;
        }
        sum0 += __shfl_xor_sync(0xffffffffu, sum0, 1);
        sum0 += __shfl_xor_sync(0xffffffffu, sum0, 2);
        sum1 += __shfl_xor_sync(0xffffffffu, sum1, 1);
        sum1 += __shfl_xor_sync(0xffffffffu, sum1, 2);
        l0 = l0 * al0 + sum0;
        l1 = l1 * al1 + sum1;

        // O += P @ V, P A-frags via quad shfl transpose
#pragma unroll
        for (int kk = 0; kk < 8; kk++) {
            float e0 = __shfl_sync(0xffffffffu, s[kk][0], srcq0);
            float e1 = __shfl_sync(0xffffffffu, s[kk][1], srcq0);
            float e2 = __shfl_sync(0xffffffffu, s[kk][2], srcq0);
            float e3 = __shfl_sync(0xffffffffu, s[kk][3], srcq0);
            float f0 = __shfl_sync(0xffffffffu, s[kk][0], srcq1);
            float f1 = __shfl_sync(0xffffffffu, s[kk][1], srcq1);
            float f2 = __shfl_sync(0xffffffffu, s[kk][2], srcq1);
            float f3 = __shfl_sync(0xffffffffu, s[kk][3], srcq1);
            uint32_t pa0 = f32_tf32(odd ? e1 : e0);
            uint32_t pa1 = f32_tf32(odd ? e3 : e2);
            uint32_t pa2 = f32_tf32(odd ? f1 : f0);
            uint32_t pa3 = f32_tf32(odd ? f3 : f2);
#pragma unroll
            for (int p = 0; p < 4; p++) {
                uint32_t b0, b1, b2, b3;
                ldm_x4(b0, b1, b2, b3, v_addr + p * (16 * FST * 4) + kk * 32);
                mma_tf32(o[2 * p],     pa0, pa1, pa2, pa3, b0, b1);
                mma_tf32(o[2 * p + 1], pa0, pa1, pa2, pa3, b2, b3);
            }
        }
        __syncthreads();
    }

    const float inv0 = 1.0f / l0;
    const float inv1 = 1.0f / l1;
    const size_t r0 = (size_t)(b * NT + t0 + qbase + g) * NC + h * HD;
    const size_t r1 = r0 + (size_t)8 * NC;
#pragma unroll
    for (int ni = 0; ni < 8; ni++) {
        const int col = ni * 8 + 2 * tg;
        *(float2*)(g_o + r0 + col) = make_float2(
            __uint_as_float(f32_tf32(o[ni][0] * inv0)),
            __uint_as_float(f32_tf32(o[ni][1] * inv0)));
        *(float2*)(g_o + r1 + col) = make_float2(
            __uint_as_float(f32_tf32(o[ni][2] * inv1)),
            __uint_as_float(f32_tf32(o[ni][3] * inv1)));
    }
}

// ---------------- launch ------------------------------------------------------
extern "C" void kernel_launch(void* const* d_in, const int* in_sizes, int n_in,
                              void* d_out, int out_size)
{
    const float* x      = (const float*)d_in[0];
    const float* w_qkv  = (const float*)d_in[1];
    const float* b_qkv  = (const float*)d_in[2];
    const float* w_proj = (const float*)d_in[3];
    const float* b_proj = (const float*)d_in[4];
    float* out = (float*)d_out;

    float *p_qkv, *p_o, *p_xr, *p_w1t, *p_w2t;
    cudaGetSymbolAddress((void**)&p_qkv, g_qkv);
    cudaGetSymbolAddress((void**)&p_o,   g_o);
    cudaGetSymbolAddress((void**)&p_xr,  g_xr);
    cudaGetSymbolAddress((void**)&p_w1t, g_w1t);
    cudaGetSymbolAddress((void**)&p_w2t, g_w2t);

    const int gemm_smem  = 2 * GSTAGE * 4;        // 73728 B
    const int flash_smem = 2 * FBUF * 4;          // 69632 B
    cudaFuncSetAttribute(gemm_tf32, cudaFuncAttributeMaxDynamicSharedMemorySize,
                         gemm_smem);
    cudaFuncSetAttribute(flash_tf32, cudaFuncAttributeMaxDynamicSharedMemorySize,
                         flash_smem);

    // 0) prep: round x; transpose+round weights to [N][K]
    round_tf32<<<(NM * NC) / 1024, 256>>>(x, p_xr);
    {
        dim3 grid(N3C / 32, NC / 32);
        transpose_round<<<grid, 256>>>(w_qkv, p_w1t, NC, N3C);
    }
    {
        dim3 grid(NC / 32, NC / 32);
        transpose_round<<<grid, 256>>>(w_proj, p_w2t, NC, NC);
    }

    // 1) qkv = x @ w_qkv + b_qkv
    {
        dim3 grid(N3C / 128, NM / 128);
        gemm_tf32<<<grid, 256, gemm_smem>>>(p_xr, p_w1t, b_qkv, p_qkv, NM, N3C, NC);
    }
    // 2) rope Q,K
    {
        const int total_pairs = NM * NH * (HD / 2);
        rope_split<<<total_pairs / 256, 256>>>();
    }
    // 3) V -> [B,H,D,T]
    {
        dim3 grid(NT / 64, NH, NB);
        transpose_v<<<grid, 256>>>();
    }
    // 4) flash attention
    {
        dim3 grid(NT / 128, NH, NB);
        flash_tf32<<<grid, 256, flash_smem>>>();
    }
    // 5) out = g_o @ w_proj + b_proj
    {
        dim3 grid(NC / 128, NM / 128);
        gemm_tf32<<<grid, 256, gemm_smem>>>(p_o, p_w2t, b_proj, out, NM, NC, NC);
    }
}

// round 6
// speedup vs baseline: 4.1263x; 1.0106x over previous
#include <cuda_runtime.h>
#include <math.h>
#include <stdint.h>

// Problem constants (fixed shapes)
#define NB 4
#define NT 2048
#define NH 16
#define NC 1024
#define HD 64
#define NM (NB*NT)         // 8192
#define N3C (3*NC)         // 3072

// ---------------- scratch ----------------------------------------------------
__device__ float g_qkv[(size_t)NM * N3C];
__device__ float g_q[(size_t)NB * NH * NT * HD];
__device__ float g_k[(size_t)NB * NH * NT * HD];
__device__ float g_v[(size_t)NB * NH * NT * HD];   // V tf32, [B,H,D,T]
__device__ float g_o[(size_t)NM * NC];             // attn out (tf32-rounded)
__device__ float g_xr[(size_t)NM * NC];            // x rounded to tf32
__device__ float g_w1t[(size_t)N3C * NC];          // w_qkv^T rounded
__device__ float g_w2t[(size_t)NC * NC];           // w_proj^T rounded

// ---------------- helpers ----------------------------------------------------
__device__ __forceinline__ uint32_t f32_tf32(float x) {
    uint32_t r;
    asm("cvt.rna.tf32.f32 %0, %1;" : "=r"(r) : "f"(x));
    return r;
}

__device__ __forceinline__ void mma_tf32(float c[4],
                                         uint32_t a0, uint32_t a1, uint32_t a2, uint32_t a3,
                                         uint32_t b0, uint32_t b1) {
    asm volatile(
        "mma.sync.aligned.m16n8k8.row.col.f32.tf32.tf32.f32 "
        "{%0,%1,%2,%3}, {%4,%5,%6,%7}, {%8,%9}, {%0,%1,%2,%3};\n"
        : "+f"(c[0]), "+f"(c[1]), "+f"(c[2]), "+f"(c[3])
        : "r"(a0), "r"(a1), "r"(a2), "r"(a3), "r"(b0), "r"(b1));
}

__device__ __forceinline__ void ldm_x4(uint32_t& r0, uint32_t& r1,
                                       uint32_t& r2, uint32_t& r3, uint32_t addr) {
    asm volatile("ldmatrix.sync.aligned.m8n8.x4.shared.b16 {%0,%1,%2,%3}, [%4];"
                 : "=r"(r0), "=r"(r1), "=r"(r2), "=r"(r3) : "r"(addr));
}

__device__ __forceinline__ void cp16(uint32_t smem_addr, const void* gptr) {
    asm volatile("cp.async.cg.shared.global [%0], [%1], 16;\n"
                 :: "r"(smem_addr), "l"(gptr));
}
__device__ __forceinline__ void cp_commit() {
    asm volatile("cp.async.commit_group;\n");
}
template <int N>
__device__ __forceinline__ void cp_wait() {
    asm volatile("cp.async.wait_group %0;\n" :: "n"(N));
}
__device__ __forceinline__ uint32_t smem_u32(const void* p) {
    return (uint32_t)__cvta_generic_to_shared(p);
}

// ---------------- tf32 pre-round ---------------------------------------------
__global__ __launch_bounds__(256) void round_tf32(const float* __restrict__ in,
                                                  float* __restrict__ out) {
    const size_t i = ((size_t)blockIdx.x * 256 + threadIdx.x) * 4;
    float4 v = *(const float4*)(in + i);
    float4 o;
    o.x = __uint_as_float(f32_tf32(v.x));
    o.y = __uint_as_float(f32_tf32(v.y));
    o.z = __uint_as_float(f32_tf32(v.z));
    o.w = __uint_as_float(f32_tf32(v.w));
    *(float4*)(out + i) = o;
}

// transpose + round: in [R][Cc] -> out [Cc][R], rna-tf32
__global__ __launch_bounds__(256) void transpose_round(const float* __restrict__ in,
                                                       float* __restrict__ out,
                                                       int R, int Cc) {
    __shared__ float t[32][33];
    const int c0 = blockIdx.x * 32, r0 = blockIdx.y * 32;
    const int tx = threadIdx.x & 31, ty = threadIdx.x >> 5;
#pragma unroll
    for (int i = 0; i < 32; i += 8)
        t[ty + i][tx] = in[(size_t)(r0 + ty + i) * Cc + c0 + tx];
    __syncthreads();
#pragma unroll
    for (int i = 0; i < 32; i += 8)
        out[(size_t)(c0 + ty + i) * R + r0 + tx] =
            __uint_as_float(f32_tf32(t[tx][ty + i]));
}

// ---------------- tf32 GEMM, 3-stage cp.async, single sync per K-step --------
// C[M,N] = A[M,K] @ Bt[N,K]^T + bias. Block 128x128, K-step 32, 256 threads.
#define GST 36
#define GSTAGE (2 * 128 * GST)     // words per stage = 9216 (36864 B)

__global__ __launch_bounds__(256) void gemm_tf32(
    const float* __restrict__ A, const float* __restrict__ Bt,
    const float* __restrict__ bias, float* __restrict__ C,
    int M, int N, int K)
{
    extern __shared__ uint32_t gsm[];

    const int bx = blockIdx.x, by = blockIdx.y;
    const int tid = threadIdx.x;
    const int lane = tid & 31, wid = tid >> 5;
    const int wm = (wid & 3) * 32;
    const int wn = (wid >> 2) * 64;

    const uint32_t smem_base = smem_u32(gsm);

    const int ltile = lane >> 3, lr = lane & 7;
    const uint32_t a_off = ((wm + (ltile & 1) * 8 + lr) * GST + (ltile >> 1) * 4) * 4;
    const uint32_t b_off = ((wn + (ltile >> 1) * 8 + lr) * GST + (ltile & 1) * 4) * 4;

    const float* Ab  = A  + (size_t)(by * 128) * K;
    const float* Btb = Bt + (size_t)(bx * 128) * K;

    auto load_stage = [&](int k0, int st) {
        const uint32_t base = smem_base + (uint32_t)st * GSTAGE * 4;
#pragma unroll
        for (int t = 0; t < 4; t++) {
            const int ci = tid + t * 256;          // 0..1023
            const int row = ci >> 3, cw = (ci & 7) * 4;
            cp16(base + (row * GST + cw) * 4,
                 Ab + (size_t)row * K + k0 + cw);
            cp16(base + (128 * GST + row * GST + cw) * 4,
                 Btb + (size_t)row * K + k0 + cw);
        }
    };

    float c[2][8][4];
#pragma unroll
    for (int mi = 0; mi < 2; mi++)
#pragma unroll
        for (int ni = 0; ni < 8; ni++)
#pragma unroll
            for (int j = 0; j < 4; j++) c[mi][ni][j] = 0.f;

    const int nsteps = K / 32;
    load_stage(0, 0);
    cp_commit();
    load_stage(32, 1);
    cp_commit();

    int stg = 0;         // s % 3
    int nstg = 2;        // (s+2) % 3
    for (int s = 0; s < nsteps; s++) {
        if (s < nsteps - 1) cp_wait<1>(); else cp_wait<0>();
        __syncthreads();
        if (s + 2 < nsteps) load_stage((s + 2) * 32, nstg);
        cp_commit();

        const uint32_t sb = smem_base + (uint32_t)stg * GSTAGE * 4;
        const uint32_t a_addr = sb + a_off;
        const uint32_t b_addr = sb + 128 * GST * 4 + b_off;

#pragma unroll
        for (int kk = 0; kk < 4; kk++) {
            uint32_t a[2][4];
#pragma unroll
            for (int mi = 0; mi < 2; mi++)
                ldm_x4(a[mi][0], a[mi][1], a[mi][2], a[mi][3],
                       a_addr + mi * (16 * GST * 4) + kk * 32);
#pragma unroll
            for (int p = 0; p < 4; p++) {
                uint32_t b0, b1, b2, b3;
                ldm_x4(b0, b1, b2, b3, b_addr + p * (16 * GST * 4) + kk * 32);
                mma_tf32(c[0][2 * p],     a[0][0], a[0][1], a[0][2], a[0][3], b0, b1);
                mma_tf32(c[0][2 * p + 1], a[0][0], a[0][1], a[0][2], a[0][3], b2, b3);
                mma_tf32(c[1][2 * p],     a[1][0], a[1][1], a[1][2], a[1][3], b0, b1);
                mma_tf32(c[1][2 * p + 1], a[1][0], a[1][1], a[1][2], a[1][3], b2, b3);
            }
        }
        stg = (stg == 2) ? 0 : stg + 1;
        nstg = (nstg == 2) ? 0 : nstg + 1;
    }

    // epilogue
    const int gg = lane >> 2, tt = lane & 3;
#pragma unroll
    for (int mi = 0; mi < 2; mi++) {
        const int r0 = by * 128 + wm + mi * 16 + gg;
#pragma unroll
        for (int ni = 0; ni < 8; ni++) {
            const int col = bx * 128 + wn + ni * 8 + 2 * tt;
            const float bz0 = bias[col], bz1 = bias[col + 1];
            *(float2*)(C + (size_t)r0 * N + col) =
                make_float2(c[mi][ni][0] + bz0, c[mi][ni][1] + bz1);
            *(float2*)(C + (size_t)(r0 + 8) * N + col) =
                make_float2(c[mi][ni][2] + bz0, c[mi][ni][3] + bz1);
        }
    }
}

// ---------------- RoPE + split Q/K into [B,H,T,D] (tf32-rounded) -------------
__global__ __launch_bounds__(256) void rope_split(void)
{
    const int p = blockIdx.x * blockDim.x + threadIdx.x;
    const int i   = p & 31;
    const int h   = (p >> 5) & 15;
    const int row = p >> 9;
    const int t   = row & (NT - 1);
    const int b   = row >> 11;

    const float inv_freq = __expf(-(float)(2 * i) * (9.210340371976184f / (float)HD));
    const float theta = (float)t * inv_freq;
    float sn, cs;
    sincosf(theta, &sn, &cs);

    const size_t base = (size_t)row * N3C + h * HD + 2 * i;
    const float q0 = g_qkv[base],      q1 = g_qkv[base + 1];
    const float k0 = g_qkv[base + NC], k1 = g_qkv[base + NC + 1];

    const size_t oidx = (((size_t)(b * NH + h) * NT + t) * HD) + 2 * i;
    g_q[oidx]     = __uint_as_float(f32_tf32(q0 * cs - q1 * sn));
    g_q[oidx + 1] = __uint_as_float(f32_tf32(q1 * cs + q0 * sn));
    g_k[oidx]     = __uint_as_float(f32_tf32(k0 * cs - k1 * sn));
    g_k[oidx + 1] = __uint_as_float(f32_tf32(k1 * cs + k0 * sn));
}

// ---------------- V transpose: qkv[:, 2C + h*64 + d] -> g_v [B,H,D,T] --------
#define TS 67
__global__ __launch_bounds__(256) void transpose_v(void)
{
    __shared__ float Ts[64 * TS];
    const int t0 = blockIdx.x * 64;
    const int h  = blockIdx.y;
    const int b  = blockIdx.z;
    const int tid = threadIdx.x;

#pragma unroll
    for (int p = 0; p < 4; p++) {
        const int lin = tid + p * 256;
        const int trow = lin >> 4;
        const int c4 = (lin & 15) * 4;
        float4 v = *(const float4*)(g_qkv + (size_t)(b * NT + t0 + trow) * N3C
                                    + 2 * NC + h * HD + c4);
        Ts[trow * TS + c4 + 0] = __uint_as_float(f32_tf32(v.x));
        Ts[trow * TS + c4 + 1] = __uint_as_float(f32_tf32(v.y));
        Ts[trow * TS + c4 + 2] = __uint_as_float(f32_tf32(v.z));
        Ts[trow * TS + c4 + 3] = __uint_as_float(f32_tf32(v.w));
    }
    __syncthreads();

#pragma unroll
    for (int p = 0; p < 4; p++) {
        const int lin = tid + p * 256;
        const int d  = lin >> 4;
        const int t4 = (lin & 15) * 4;
        float4 o;
        o.x = Ts[(t4 + 0) * TS + d];
        o.y = Ts[(t4 + 1) * TS + d];
        o.z = Ts[(t4 + 2) * TS + d];
        o.w = Ts[(t4 + 3) * TS + d];
        *(float4*)(g_v + ((size_t)(b * NH + h) * HD + d) * NT + t0 + t4) = o;
    }
}

// ---------------- Flash attention, 3-stage cp.async, single sync per tile ----
#define FST 68
#define FBUF (2 * 64 * FST)        // words per stage (K tile + V tile) = 8704

__global__ __launch_bounds__(256) void flash_tf32(void)
{
    extern __shared__ uint32_t fsm[];

    const int qt = blockIdx.x, h = blockIdx.y, b = blockIdx.z;
    const int t0 = qt * 128;
    const int tid = threadIdx.x;
    const int lane = tid & 31, wid = tid >> 5;
    const int g = lane >> 2, tg = lane & 3;
    const int qbase = wid * 16;

    const float* Qb  = g_q + (size_t)(b * NH + h) * NT * HD;
    const float* Kb  = g_k + (size_t)(b * NH + h) * NT * HD;
    const float* Vtb = g_v + (size_t)(b * NH + h) * HD * NT;

    const uint32_t smem_base = smem_u32(fsm);

    const int ltile = lane >> 3, lr = lane & 7;
    const uint32_t fb_off = (((ltile >> 1) * 8 + lr) * FST + (ltile & 1) * 4) * 4;

    // stage Q tile [128][64] into stages 0+1 area (exactly FBUF words)
#pragma unroll
    for (int p = 0; p < 8; p++) {
        const int lin = tid + p * 256;
        const int row = lin >> 4;
        const int c4 = (lin & 15) * 4;
        float4 q4 = *(const float4*)(Qb + (size_t)(t0 + row) * HD + c4);
        fsm[row * FST + c4 + 0] = __float_as_uint(q4.x);
        fsm[row * FST + c4 + 1] = __float_as_uint(q4.y);
        fsm[row * FST + c4 + 2] = __float_as_uint(q4.z);
        fsm[row * FST + c4 + 3] = __float_as_uint(q4.w);
    }
    __syncthreads();

    uint32_t qa[8][4];
#pragma unroll
    for (int kk = 0; kk < 8; kk++) {
        const int kb = kk * 8;
        qa[kk][0] = fsm[(qbase + g)     * FST + kb + tg];
        qa[kk][1] = fsm[(qbase + 8 + g) * FST + kb + tg];
        qa[kk][2] = fsm[(qbase + g)     * FST + kb + 4 + tg];
        qa[kk][3] = fsm[(qbase + 8 + g) * FST + kb + 4 + tg];
    }
    __syncthreads();   // all qa reads done before stage 0/1 overwrite

    auto load_tile = [&](int kt, int buf) {
        const uint32_t base = smem_base + (uint32_t)buf * FBUF * 4;
#pragma unroll
        for (int p = 0; p < 4; p++) {
            const int lin = tid + p * 256;
            const int row = lin >> 4;
            const int c4 = (lin & 15) * 4;
            cp16(base + (row * FST + c4) * 4,
                 Kb + (size_t)(kt * 64 + row) * HD + c4);
            cp16(base + (64 * FST + row * FST + c4) * 4,
                 Vtb + (size_t)row * NT + kt * 64 + c4);
        }
    };

    float o[8][4];
#pragma unroll
    for (int ni = 0; ni < 8; ni++)
#pragma unroll
        for (int j = 0; j < 4; j++) o[ni][j] = 0.f;
    float m0 = -INFINITY, m1 = -INFINITY, l0 = 0.f, l1 = 0.f;
    const float scale = 0.125f;

    load_tile(0, 0);
    cp_commit();
    load_tile(1, 1);
    cp_commit();

    const int srcq0 = (lane & ~3) | (tg >> 1);
    const int srcq1 = srcq0 + 2;
    const bool odd = (tg & 1);

    const int NITER = NT / 64;
    int stg = 0, nstg = 2;
    for (int kt = 0; kt < NITER; kt++) {
        if (kt < NITER - 1) cp_wait<1>(); else cp_wait<0>();
        __syncthreads();
        if (kt + 2 < NITER) load_tile(kt + 2, nstg);
        cp_commit();

        const uint32_t k_addr = smem_base + (uint32_t)stg * FBUF * 4 + fb_off;
        const uint32_t v_addr = k_addr + 64 * FST * 4;

        // S = Q @ K^T
        float s[8][4];
#pragma unroll
        for (int ni = 0; ni < 8; ni++)
#pragma unroll
            for (int j = 0; j < 4; j++) s[ni][j] = 0.f;

#pragma unroll
        for (int kk = 0; kk < 8; kk++) {
#pragma unroll
            for (int p = 0; p < 4; p++) {
                uint32_t b0, b1, b2, b3;
                ldm_x4(b0, b1, b2, b3, k_addr + p * (16 * FST * 4) + kk * 32);
                mma_tf32(s[2 * p],     qa[kk][0], qa[kk][1], qa[kk][2], qa[kk][3], b0, b1);
                mma_tf32(s[2 * p + 1], qa[kk][0], qa[kk][1], qa[kk][2], qa[kk][3], b2, b3);
            }
        }

        // online softmax (rows g and g+8)
        float mx0 = -INFINITY, mx1 = -INFINITY;
#pragma unroll
        for (int ni = 0; ni < 8; ni++) {
            s[ni][0] *= scale; s[ni][1] *= scale; s[ni][2] *= scale; s[ni][3] *= scale;
            mx0 = fmaxf(mx0, fmaxf(s[ni][0], s[ni][1]));
            mx1 = fmaxf(mx1, fmaxf(s[ni][2], s[ni][3]));
        }
        mx0 = fmaxf(mx0, __shfl_xor_sync(0xffffffffu, mx0, 1));
        mx0 = fmaxf(mx0, __shfl_xor_sync(0xffffffffu, mx0, 2));
        mx1 = fmaxf(mx1, __shfl_xor_sync(0xffffffffu, mx1, 1));
        mx1 = fmaxf(mx1, __shfl_xor_sync(0xffffffffu, mx1, 2));

        const float mn0 = fmaxf(m0, mx0);
        const float mn1 = fmaxf(m1, mx1);
        const float al0 = __expf(m0 - mn0);
        const float al1 = __expf(m1 - mn1);
        m0 = mn0; m1 = mn1;

        float sum0 = 0.f, sum1 = 0.f;
#pragma unroll
        for (int ni = 0; ni < 8; ni++) {
            s[ni][0] = __expf(s[ni][0] - mn0);
            s[ni][1] = __expf(s[ni][1] - mn0);
            s[ni][2] = __expf(s[ni][2] - mn1);
            s[ni][3] = __expf(s[ni][3] - mn1);
            sum0 += s[ni][0] + s[ni][1];
            sum1 += s[ni][2] + s[ni][3];
            o[ni][0] *= al0; o[ni][1] *= al0; o[ni][2] *= al1; o[ni][3] *= al1;
        }
        sum0 += __shfl_xor_sync(0xffffffffu, sum0, 1);
        sum0 += __shfl_xor_sync(0xffffffffu, sum0, 2);
        sum1 += __shfl_xor_sync(0xffffffffu, sum1, 1);
        sum1 += __shfl_xor_sync(0xffffffffu, sum1, 2);
        l0 = l0 * al0 + sum0;
        l1 = l1 * al1 + sum1;

        // O += P @ V, P A-frags via quad shfl transpose
#pragma unroll
        for (int kk = 0; kk < 8; kk++) {
            float e0 = __shfl_sync(0xffffffffu, s[kk][0], srcq0);
            float e1 = __shfl_sync(0xffffffffu, s[kk][1], srcq0);
            float e2 = __shfl_sync(0xffffffffu, s[kk][2], srcq0);
            float e3 = __shfl_sync(0xffffffffu, s[kk][3], srcq0);
            float f0 = __shfl_sync(0xffffffffu, s[kk][0], srcq1);
            float f1 = __shfl_sync(0xffffffffu, s[kk][1], srcq1);
            float f2 = __shfl_sync(0xffffffffu, s[kk][2], srcq1);
            float f3 = __shfl_sync(0xffffffffu, s[kk][3], srcq1);
            uint32_t pa0 = f32_tf32(odd ? e1 : e0);
            uint32_t pa1 = f32_tf32(odd ? e3 : e2);
            uint32_t pa2 = f32_tf32(odd ? f1 : f0);
            uint32_t pa3 = f32_tf32(odd ? f3 : f2);
#pragma unroll
            for (int p = 0; p < 4; p++) {
                uint32_t b0, b1, b2, b3;
                ldm_x4(b0, b1, b2, b3, v_addr + p * (16 * FST * 4) + kk * 32);
                mma_tf32(o[2 * p],     pa0, pa1, pa2, pa3, b0, b1);
                mma_tf32(o[2 * p + 1], pa0, pa1, pa2, pa3, b2, b3);
            }
        }

        stg = (stg == 2) ? 0 : stg + 1;
        nstg = (nstg == 2) ? 0 : nstg + 1;
    }

    const float inv0 = 1.0f / l0;
    const float inv1 = 1.0f / l1;
    const size_t r0 = (size_t)(b * NT + t0 + qbase + g) * NC + h * HD;
    const size_t r1 = r0 + (size_t)8 * NC;
#pragma unroll
    for (int ni = 0; ni < 8; ni++) {
        const int col = ni * 8 + 2 * tg;
        *(float2*)(g_o + r0 + col) = make_float2(
            __uint_as_float(f32_tf32(o[ni][0] * inv0)),
            __uint_as_float(f32_tf32(o[ni][1] * inv0)));
        *(float2*)(g_o + r1 + col) = make_float2(
            __uint_as_float(f32_tf32(o[ni][2] * inv1)),
            __uint_as_float(f32_tf32(o[ni][3] * inv1)));
    }
}

// ---------------- launch ------------------------------------------------------
extern "C" void kernel_launch(void* const* d_in, const int* in_sizes, int n_in,
                              void* d_out, int out_size)
{
    const float* x      = (const float*)d_in[0];
    const float* w_qkv  = (const float*)d_in[1];
    const float* b_qkv  = (const float*)d_in[2];
    const float* w_proj = (const float*)d_in[3];
    const float* b_proj = (const float*)d_in[4];
    float* out = (float*)d_out;

    float *p_qkv, *p_o, *p_xr, *p_w1t, *p_w2t;
    cudaGetSymbolAddress((void**)&p_qkv, g_qkv);
    cudaGetSymbolAddress((void**)&p_o,   g_o);
    cudaGetSymbolAddress((void**)&p_xr,  g_xr);
    cudaGetSymbolAddress((void**)&p_w1t, g_w1t);
    cudaGetSymbolAddress((void**)&p_w2t, g_w2t);

    const int gemm_smem  = 3 * GSTAGE * 4;        // 110592 B
    const int flash_smem = 3 * FBUF * 4;          // 104448 B
    cudaFuncSetAttribute(gemm_tf32, cudaFuncAttributeMaxDynamicSharedMemorySize,
                         gemm_smem);
    cudaFuncSetAttribute(flash_tf32, cudaFuncAttributeMaxDynamicSharedMemorySize,
                         flash_smem);

    // 0) prep: round x; transpose+round weights to [N][K]
    round_tf32<<<(NM * NC) / 1024, 256>>>(x, p_xr);
    {
        dim3 grid(N3C / 32, NC / 32);
        transpose_round<<<grid, 256>>>(w_qkv, p_w1t, NC, N3C);
    }
    {
        dim3 grid(NC / 32, NC / 32);
        transpose_round<<<grid, 256>>>(w_proj, p_w2t, NC, NC);
    }

    // 1) qkv = x @ w_qkv + b_qkv
    {
        dim3 grid(N3C / 128, NM / 128);
        gemm_tf32<<<grid, 256, gemm_smem>>>(p_xr, p_w1t, b_qkv, p_qkv, NM, N3C, NC);
    }
    // 2) rope Q,K
    {
        const int total_pairs = NM * NH * (HD / 2);
        rope_split<<<total_pairs / 256, 256>>>();
    }
    // 3) V -> [B,H,D,T]
    {
        dim3 grid(NT / 64, NH, NB);
        transpose_v<<<grid, 256>>>();
    }
    // 4) flash attention
    {
        dim3 grid(NT / 128, NH, NB);
        flash_tf32<<<grid, 256, flash_smem>>>();
    }
    // 5) out = g_o @ w_proj + b_proj
    {
        dim3 grid(NC / 128, NM / 128);
        gemm_tf32<<<grid, 256, gemm_smem>>>(p_o, p_w2t, b_proj, out, NM, NC, NC);
    }
}

// round 10
// speedup vs baseline: 7.7294x; 1.8732x over previous
#include <cuda_runtime.h>
#include <cuda_fp16.h>
#include <math.h>
#include <stdint.h>

// Problem constants (fixed shapes)
#define NB 4
#define NT 2048
#define NH 16
#define NC 1024
#define HD 64
#define NM (NB*NT)         // 8192
#define N3C (3*NC)         // 3072

// ---------------- scratch ----------------------------------------------------
__device__ float  g_qkv[(size_t)NM * N3C];          // fp32 qkv
__device__ __half g_q[(size_t)NB * NH * NT * HD];   // rope(Q)*0.125, fp16 [B,H,T,D]
__device__ __half g_k[(size_t)NB * NH * NT * HD];   // rope(K), fp16 [B,H,T,D]
__device__ __half g_v[(size_t)NB * NH * NT * HD];   // V fp16, [B,H,D,T]
__device__ __half g_oh[(size_t)NM * NC];            // attn out fp16
__device__ __half g_xh[(size_t)NM * NC];            // x fp16
__device__ __half g_w1t[(size_t)N3C * NC];          // w_qkv^T fp16 [3072][1024]
__device__ __half g_w2t[(size_t)NC * NC];           // w_proj^T fp16

// ---------------- helpers ----------------------------------------------------
__device__ __forceinline__ uint32_t pack2(float lo, float hi) {
    __half2 h = __floats2half2_rn(lo, hi);
    return *reinterpret_cast<uint32_t*>(&h);
}

__device__ __forceinline__ void mma_fp16(float c[4],
                                         uint32_t a0, uint32_t a1, uint32_t a2, uint32_t a3,
                                         uint32_t b0, uint32_t b1) {
    asm volatile(
        "mma.sync.aligned.m16n8k16.row.col.f32.f16.f16.f32 "
        "{%0,%1,%2,%3}, {%4,%5,%6,%7}, {%8,%9}, {%0,%1,%2,%3};\n"
        : "+f"(c[0]), "+f"(c[1]), "+f"(c[2]), "+f"(c[3])
        : "r"(a0), "r"(a1), "r"(a2), "r"(a3), "r"(b0), "r"(b1));
}

__device__ __forceinline__ void ldm_x4(uint32_t& r0, uint32_t& r1,
                                       uint32_t& r2, uint32_t& r3, uint32_t addr) {
    asm volatile("ldmatrix.sync.aligned.m8n8.x4.shared.b16 {%0,%1,%2,%3}, [%4];"
                 : "=r"(r0), "=r"(r1), "=r"(r2), "=r"(r3) : "r"(addr));
}

__device__ __forceinline__ void cp16(uint32_t smem_addr, const void* gptr) {
    asm volatile("cp.async.cg.shared.global [%0], [%1], 16;\n"
                 :: "r"(smem_addr), "l"(gptr));
}
__device__ __forceinline__ void cp_commit() {
    asm volatile("cp.async.commit_group;\n");
}
template <int N>
__device__ __forceinline__ void cp_wait() {
    asm volatile("cp.async.wait_group %0;\n" :: "n"(N));
}
__device__ __forceinline__ uint32_t smem_u32(const void* p) {
    return (uint32_t)__cvta_generic_to_shared(p);
}

// ---------------- prep kernels -----------------------------------------------
__global__ __launch_bounds__(256) void round_half(const float* __restrict__ in,
                                                  __half* __restrict__ out) {
    const size_t i = ((size_t)blockIdx.x * 256 + threadIdx.x) * 4;
    float4 v = *(const float4*)(in + i);
    uint2 o;
    o.x = pack2(v.x, v.y);
    o.y = pack2(v.z, v.w);
    *(uint2*)(out + i) = o;
}

// transpose + round: in fp32 [R][Cc] -> out fp16 [Cc][R]
__global__ __launch_bounds__(256) void transpose_round_h(const float* __restrict__ in,
                                                         __half* __restrict__ out,
                                                         int R, int Cc) {
    __shared__ float t[32][33];
    const int c0 = blockIdx.x * 32, r0 = blockIdx.y * 32;
    const int tx = threadIdx.x & 31, ty = threadIdx.x >> 5;
#pragma unroll
    for (int i = 0; i < 32; i += 8)
        t[ty + i][tx] = in[(size_t)(r0 + ty + i) * Cc + c0 + tx];
    __syncthreads();
#pragma unroll
    for (int i = 0; i < 32; i += 8)
        out[(size_t)(c0 + ty + i) * R + r0 + tx] = __float2half_rn(t[tx][ty + i]);
}

// ---------------- fp16 GEMM, 3-stage cp.async --------------------------------
// C[M,N] = A[M,K] @ Bt[N,K]^T + bias. Block 128x128, K-step 64 halfs, 256 thr.
#define GST 72                      // halfs per smem row (36 words; banks 4r)
#define GOPB (128 * GST * 2)        // bytes per operand per stage = 18432
#define GSTB (2 * GOPB)             // stage bytes = 36864

__global__ __launch_bounds__(256) void gemm_fp16(
    const __half* __restrict__ A, const __half* __restrict__ Bt,
    const float* __restrict__ bias, float* __restrict__ C,
    int M, int N, int K)
{
    extern __shared__ uint32_t gsm[];

    const int bx = blockIdx.x, by = blockIdx.y;
    const int tid = threadIdx.x;
    const int lane = tid & 31, wid = tid >> 5;
    const int wm = (wid & 3) * 32;
    const int wn = (wid >> 2) * 64;

    const uint32_t smem_base = smem_u32(gsm);

    const int lr = lane & 7, ts = lane >> 3;
    // A tiles: (mlo,klo)(mhi,klo)(mlo,khi)(mhi,khi) -> a0..a3
    const uint32_t a_off = ((wm + (ts & 1) * 8 + lr) * GST + (ts >> 1) * 8) * 2;
    // B tiles: (nlo,klo)(nlo,khi)(nhi,klo)(nhi,khi) -> b0..b3
    const uint32_t b_off = ((wn + (ts >> 1) * 8 + lr) * GST + (ts & 1) * 8) * 2;

    const __half* Ab  = A  + (size_t)(by * 128) * K;
    const __half* Btb = Bt + (size_t)(bx * 128) * K;

    auto load_stage = [&](int k0, int st) {
        const uint32_t base = smem_base + (uint32_t)st * GSTB;
#pragma unroll
        for (int t = 0; t < 4; t++) {
            const int ci = tid + t * 256;          // 0..1023
            const int row = ci >> 3, cw = (ci & 7) * 8;   // halfs
            cp16(base + (row * GST + cw) * 2,
                 Ab + (size_t)row * K + k0 + cw);
            cp16(base + GOPB + (row * GST + cw) * 2,
                 Btb + (size_t)row * K + k0 + cw);
        }
    };

    float c[2][8][4];
#pragma unroll
    for (int mi = 0; mi < 2; mi++)
#pragma unroll
        for (int ni = 0; ni < 8; ni++)
#pragma unroll
            for (int j = 0; j < 4; j++) c[mi][ni][j] = 0.f;

    const int nsteps = K / 64;
    load_stage(0, 0);
    cp_commit();
    load_stage(64, 1);
    cp_commit();

    int stg = 0, nstg = 2;
    for (int s = 0; s < nsteps; s++) {
        if (s < nsteps - 1) cp_wait<1>(); else cp_wait<0>();
        __syncthreads();
        if (s + 2 < nsteps) load_stage((s + 2) * 64, nstg);
        cp_commit();

        const uint32_t sb = smem_base + (uint32_t)stg * GSTB;
        const uint32_t a_addr = sb + a_off;
        const uint32_t b_addr = sb + GOPB + b_off;

#pragma unroll
        for (int kk = 0; kk < 4; kk++) {         // 4 x k16
            uint32_t a[2][4];
#pragma unroll
            for (int mi = 0; mi < 2; mi++)
                ldm_x4(a[mi][0], a[mi][1], a[mi][2], a[mi][3],
                       a_addr + mi * (16 * GST * 2) + kk * 32);
#pragma unroll
            for (int p = 0; p < 4; p++) {
                uint32_t b0, b1, b2, b3;
                ldm_x4(b0, b1, b2, b3, b_addr + p * (16 * GST * 2) + kk * 32);
                mma_fp16(c[0][2 * p],     a[0][0], a[0][1], a[0][2], a[0][3], b0, b1);
                mma_fp16(c[0][2 * p + 1], a[0][0], a[0][1], a[0][2], a[0][3], b2, b3);
                mma_fp16(c[1][2 * p],     a[1][0], a[1][1], a[1][2], a[1][3], b0, b1);
                mma_fp16(c[1][2 * p + 1], a[1][0], a[1][1], a[1][2], a[1][3], b2, b3);
            }
        }
        stg = (stg == 2) ? 0 : stg + 1;
        nstg = (nstg == 2) ? 0 : nstg + 1;
    }

    // epilogue: bias + fp32 store
    const int gg = lane >> 2, tt = lane & 3;
#pragma unroll
    for (int mi = 0; mi < 2; mi++) {
        const int r0 = by * 128 + wm + mi * 16 + gg;
#pragma unroll
        for (int ni = 0; ni < 8; ni++) {
            const int col = bx * 128 + wn + ni * 8 + 2 * tt;
            const float bz0 = bias[col], bz1 = bias[col + 1];
            *(float2*)(C + (size_t)r0 * N + col) =
                make_float2(c[mi][ni][0] + bz0, c[mi][ni][1] + bz1);
            *(float2*)(C + (size_t)(r0 + 8) * N + col) =
                make_float2(c[mi][ni][2] + bz0, c[mi][ni][3] + bz1);
        }
    }
}

// ---------------- RoPE + split Q/K into fp16 [B,H,T,D] -----------------------
// Q pre-scaled by 0.125 (exact power of two; folds attention scale away).
__global__ __launch_bounds__(256) void rope_split(void)
{
    const int p = blockIdx.x * blockDim.x + threadIdx.x;
    const int i   = p & 31;
    const int h   = (p >> 5) & 15;
    const int row = p >> 9;
    const int t   = row & (NT - 1);
    const int b   = row >> 11;

    const float inv_freq = __expf(-(float)(2 * i) * (9.210340371976184f / (float)HD));
    const float theta = (float)t * inv_freq;
    float sn, cs;
    sincosf(theta, &sn, &cs);

    const size_t base = (size_t)row * N3C + h * HD + 2 * i;
    const float q0 = g_qkv[base],      q1 = g_qkv[base + 1];
    const float k0 = g_qkv[base + NC], k1 = g_qkv[base + NC + 1];

    const size_t oidx = (((size_t)(b * NH + h) * NT + t) * HD) + 2 * i;
    *(uint32_t*)(g_q + oidx) = pack2((q0 * cs - q1 * sn) * 0.125f,
                                     (q1 * cs + q0 * sn) * 0.125f);
    *(uint32_t*)(g_k + oidx) = pack2(k0 * cs - k1 * sn,
                                     k1 * cs + k0 * sn);
}

// ---------------- V transpose: qkv[:, 2C + h*64 + d] -> g_v fp16 [B,H,D,T] ---
#define TS 67
__global__ __launch_bounds__(256) void transpose_v(void)
{
    __shared__ float Ts[64 * TS];
    const int t0 = blockIdx.x * 64;
    const int h  = blockIdx.y;
    const int b  = blockIdx.z;
    const int tid = threadIdx.x;

#pragma unroll
    for (int p = 0; p < 4; p++) {
        const int lin = tid + p * 256;
        const int trow = lin >> 4;
        const int c4 = (lin & 15) * 4;
        float4 v = *(const float4*)(g_qkv + (size_t)(b * NT + t0 + trow) * N3C
                                    + 2 * NC + h * HD + c4);
        Ts[trow * TS + c4 + 0] = v.x;
        Ts[trow * TS + c4 + 1] = v.y;
        Ts[trow * TS + c4 + 2] = v.z;
        Ts[trow * TS + c4 + 3] = v.w;
    }
    __syncthreads();

#pragma unroll
    for (int p = 0; p < 4; p++) {
        const int lin = tid + p * 256;
        const int d  = lin >> 4;
        const int t4 = (lin & 15) * 4;
        uint2 o;
        o.x = pack2(Ts[(t4 + 0) * TS + d], Ts[(t4 + 1) * TS + d]);
        o.y = pack2(Ts[(t4 + 2) * TS + d], Ts[(t4 + 3) * TS + d]);
        *(uint2*)(g_v + ((size_t)(b * NH + h) * HD + d) * NT + t0 + t4) = o;
    }
}

// ---------------- Flash attention, fp16 mma, 3-stage cp.async ----------------
// BQ=128 (8 warps x 16 q rows), BKV=64. P: direct C-frag -> A-frag half2 pack.
#define KOPB (64 * GST * 2)        // 9216 bytes (one 64-row tile)
#define FSTB (2 * KOPB)            // stage bytes = 18432 (K tile + V tile)

__global__ __launch_bounds__(256) void flash_fp16(void)
{
    extern __shared__ uint32_t fsm[];

    const int qt = blockIdx.x, h = blockIdx.y, b = blockIdx.z;
    const int t0 = qt * 128;
    const int tid = threadIdx.x;
    const int lane = tid & 31, wid = tid >> 5;
    const int g = lane >> 2, tg = lane & 3;
    const int qbase = wid * 16;

    const __half* Qb  = g_q + (size_t)(b * NH + h) * NT * HD;
    const __half* Kb  = g_k + (size_t)(b * NH + h) * NT * HD;
    const __half* Vtb = g_v + (size_t)(b * NH + h) * HD * NT;

    const uint32_t smem_base = smem_u32(fsm);

    const int lr = lane & 7, ts = lane >> 3;
    // A-style tiles (Q): (mlo,klo)(mhi,klo)(mlo,khi)(mhi,khi)
    const uint32_t qa_off = ((qbase + (ts & 1) * 8 + lr) * GST + (ts >> 1) * 8) * 2;
    // B-style tiles (K rows=kv, V rows=d): (nlo,klo)(nlo,khi)(nhi,klo)(nhi,khi)
    const uint32_t fb_off = (((ts >> 1) * 8 + lr) * GST + (ts & 1) * 8) * 2;

    // stage Q tile [128][64 halfs] into stage 0 (rows at stride GST)
#pragma unroll
    for (int t = 0; t < 4; t++) {
        const int ci = tid + t * 256;
        const int row = ci >> 3, cw = (ci & 7) * 8;
        cp16(smem_base + (row * GST + cw) * 2,
             Qb + (size_t)(t0 + row) * HD + cw);
    }
    cp_commit();
    cp_wait<0>();
    __syncthreads();

    uint32_t qa[4][4];
#pragma unroll
    for (int kk = 0; kk < 4; kk++)
        ldm_x4(qa[kk][0], qa[kk][1], qa[kk][2], qa[kk][3],
               smem_base + qa_off + kk * 32);
    __syncthreads();   // qa reads done before stage-0 overwrite

    auto load_tile = [&](int kt, int buf) {
        const uint32_t base = smem_base + (uint32_t)buf * FSTB;
#pragma unroll
        for (int t = 0; t < 2; t++) {
            const int ci = tid + t * 256;          // 0..511
            const int row = ci >> 3, cw = (ci & 7) * 8;
            cp16(base + (row * GST + cw) * 2,
                 Kb + (size_t)(kt * 64 + row) * HD + cw);
            cp16(base + KOPB + (row * GST + cw) * 2,
                 Vtb + (size_t)row * NT + kt * 64 + cw);
        }
    };

    float o[8][4];
#pragma unroll
    for (int ni = 0; ni < 8; ni++)
#pragma unroll
        for (int j = 0; j < 4; j++) o[ni][j] = 0.f;
    float m0 = -INFINITY, m1 = -INFINITY, l0 = 0.f, l1 = 0.f;

    load_tile(0, 0);
    cp_commit();
    load_tile(1, 1);
    cp_commit();

    const int NITER = NT / 64;
    int stg = 0, nstg = 2;
    for (int kt = 0; kt < NITER; kt++) {
        if (kt < NITER - 1) cp_wait<1>(); else cp_wait<0>();
        __syncthreads();
        if (kt + 2 < NITER) load_tile(kt + 2, nstg);
        cp_commit();

        const uint32_t k_addr = smem_base + (uint32_t)stg * FSTB + fb_off;
        const uint32_t v_addr = k_addr + KOPB;

        // S = (Q*0.125) @ K^T
        float s[8][4];
#pragma unroll
        for (int ni = 0; ni < 8; ni++)
#pragma unroll
            for (int j = 0; j < 4; j++) s[ni][j] = 0.f;

#pragma unroll
        for (int kk = 0; kk < 4; kk++) {
#pragma unroll
            for (int p = 0; p < 4; p++) {
                uint32_t b0, b1, b2, b3;
                ldm_x4(b0, b1, b2, b3, k_addr + p * (16 * GST * 2) + kk * 32);
                mma_fp16(s[2 * p],     qa[kk][0], qa[kk][1], qa[kk][2], qa[kk][3], b0, b1);
                mma_fp16(s[2 * p + 1], qa[kk][0], qa[kk][1], qa[kk][2], qa[kk][3], b2, b3);
            }
        }

        // online softmax (rows g and g+8)
        float mx0 = -INFINITY, mx1 = -INFINITY;
#pragma unroll
        for (int ni = 0; ni < 8; ni++) {
            mx0 = fmaxf(mx0, fmaxf(s[ni][0], s[ni][1]));
            mx1 = fmaxf(mx1, fmaxf(s[ni][2], s[ni][3]));
        }
        mx0 = fmaxf(mx0, __shfl_xor_sync(0xffffffffu, mx0, 1));
        mx0 = fmaxf(mx0, __shfl_xor_sync(0xffffffffu, mx0, 2));
        mx1 = fmaxf(mx1, __shfl_xor_sync(0xffffffffu, mx1, 1));
        mx1 = fmaxf(mx1, __shfl_xor_sync(0xffffffffu, mx1, 2));

        const float mn0 = fmaxf(m0, mx0);
        const float mn1 = fmaxf(m1, mx1);
        const float al0 = __expf(m0 - mn0);
        const float al1 = __expf(m1 - mn1);
        m0 = mn0; m1 = mn1;

        float sum0 = 0.f, sum1 = 0.f;
#pragma unroll
        for (int ni = 0; ni < 8; ni++) {
            s[ni][0] = __expf(s[ni][0] - mn0);
            s[ni][1] = __expf(s[ni][1] - mn0);
            s[ni][2] = __expf(s[ni][2] - mn1);
            s[ni][3] = __expf(s[ni][3] - mn1);
            sum0 += s[ni][0] + s[ni][1];
            sum1 += s[ni][2] + s[ni][3];
            o[ni][0] *= al0; o[ni][1] *= al0; o[ni][2] *= al1; o[ni][3] *= al1;
        }
        sum0 += __shfl_xor_sync(0xffffffffu, sum0, 1);
        sum0 += __shfl_xor_sync(0xffffffffu, sum0, 2);
        sum1 += __shfl_xor_sync(0xffffffffu, sum1, 1);
        sum1 += __shfl_xor_sync(0xffffffffu, sum1, 2);
        l0 = l0 * al0 + sum0;
        l1 = l1 * al1 + sum1;

        // O += P @ V : P C-frag packs DIRECTLY into fp16 A-frag (no shuffles)
#pragma unroll
        for (int kk = 0; kk < 4; kk++) {      // kv 16-chunks
            const uint32_t pa0 = pack2(s[2 * kk][0],     s[2 * kk][1]);
            const uint32_t pa1 = pack2(s[2 * kk][2],     s[2 * kk][3]);
            const uint32_t pa2 = pack2(s[2 * kk + 1][0], s[2 * kk + 1][1]);
            const uint32_t pa3 = pack2(s[2 * kk + 1][2], s[2 * kk + 1][3]);
#pragma unroll
            for (int p = 0; p < 4; p++) {     // d 16-blocks
                uint32_t b0, b1, b2, b3;
                ldm_x4(b0, b1, b2, b3, v_addr + p * (16 * GST * 2) + kk * 32);
                mma_fp16(o[2 * p],     pa0, pa1, pa2, pa3, b0, b1);
                mma_fp16(o[2 * p + 1], pa0, pa1, pa2, pa3, b2, b3);
            }
        }

        stg = (stg == 2) ? 0 : stg + 1;
        nstg = (nstg == 2) ? 0 : nstg + 1;
    }

    // epilogue: normalize, store fp16 to g_oh [B*T][C]
    const float inv0 = 1.0f / l0;
    const float inv1 = 1.0f / l1;
    const size_t r0 = (size_t)(b * NT + t0 + qbase + g) * NC + h * HD;
    const size_t r1 = r0 + (size_t)8 * NC;
#pragma unroll
    for (int ni = 0; ni < 8; ni++) {
        const int col = ni * 8 + 2 * tg;
        *(uint32_t*)(g_oh + r0 + col) = pack2(o[ni][0] * inv0, o[ni][1] * inv0);
        *(uint32_t*)(g_oh + r1 + col) = pack2(o[ni][2] * inv1, o[ni][3] * inv1);
    }
}

// ---------------- launch ------------------------------------------------------
extern "C" void kernel_launch(void* const* d_in, const int* in_sizes, int n_in,
                              void* d_out, int out_size)
{
    const float* x      = (const float*)d_in[0];
    const float* w_qkv  = (const float*)d_in[1];
    const float* b_qkv  = (const float*)d_in[2];
    const float* w_proj = (const float*)d_in[3];
    const float* b_proj = (const float*)d_in[4];
    float* out = (float*)d_out;

    float *p_qkv;
    __half *p_oh, *p_xh, *p_w1t, *p_w2t;
    cudaGetSymbolAddress((void**)&p_qkv, g_qkv);
    cudaGetSymbolAddress((void**)&p_oh,  g_oh);
    cudaGetSymbolAddress((void**)&p_xh,  g_xh);
    cudaGetSymbolAddress((void**)&p_w1t, g_w1t);
    cudaGetSymbolAddress((void**)&p_w2t, g_w2t);

    const int gemm_smem  = 3 * GSTB;     // 110592 B
    const int flash_smem = 3 * FSTB;     // 55296 B
    cudaFuncSetAttribute(gemm_fp16, cudaFuncAttributeMaxDynamicSharedMemorySize,
                         gemm_smem);
    cudaFuncSetAttribute(flash_fp16, cudaFuncAttributeMaxDynamicSharedMemorySize,
                         flash_smem);

    // 0) prep: x -> fp16; weights -> transposed fp16 [N][K]
    round_half<<<(NM * NC) / 1024, 256>>>(x, p_xh);
    {
        dim3 grid(N3C / 32, NC / 32);
        transpose_round_h<<<grid, 256>>>(w_qkv, p_w1t, NC, N3C);
    }
    {
        dim3 grid(NC / 32, NC / 32);
        transpose_round_h<<<grid, 256>>>(w_proj, p_w2t, NC, NC);
    }

    // 1) qkv = x @ w_qkv + b_qkv  (fp32 out)
    {
        dim3 grid(N3C / 128, NM / 128);
        gemm_fp16<<<grid, 256, gemm_smem>>>(p_xh, p_w1t, b_qkv, p_qkv, NM, N3C, NC);
    }
    // 2) rope Q,K -> fp16 [B,H,T,D] (Q pre-scaled by 1/8)
    {
        const int total_pairs = NM * NH * (HD / 2);
        rope_split<<<total_pairs / 256, 256>>>();
    }
    // 3) V -> fp16 [B,H,D,T]
    {
        dim3 grid(NT / 64, NH, NB);
        transpose_v<<<grid, 256>>>();
    }
    // 4) flash attention -> g_oh fp16
    {
        dim3 grid(NT / 128, NH, NB);
        flash_fp16<<<grid, 256, flash_smem>>>();
    }
    // 5) out = g_oh @ w_proj + b_proj
    {
        dim3 grid(NC / 128, NM / 128);
        gemm_fp16<<<grid, 256, gemm_smem>>>(p_oh, p_w2t, b_proj, out, NM, NC, NC);
    }
}